// round 1
// baseline (speedup 1.0000x reference)
#include <cuda_runtime.h>
#include <math.h>

// Problem constants
#define B    32
#define CDIM 128
#define NSP  4096          // 64*64 spatial
#define HEADS 4
#define DH   32            // dim_head
#define EPS  1e-5f

// Scratch (static __device__ — no allocation allowed)
__device__ float g_qkv[(size_t)B * 384 * NSP];       // 201 MB staging
__device__ float g_Sp[(size_t)B * HEADS * 8 * DH * DH]; // context partials
__device__ float g_Zp[(size_t)B * HEADS * 8 * DH];      // Z partials
__device__ float g_M[(size_t)B * CDIM * CDIM];          // fused M_b = Wout∘ctx

// ---------------------------------------------------------------------------
// Kernel 1: qkv[b] = Wqkv(384x128) @ x[b](128x4096)
// Block: 128x128 output tile, 256 threads, 8x8 microtile, K-chunks of 32.
// grid = (32 col tiles, 3 row blocks, 32 batches)
// ---------------------------------------------------------------------------
__global__ void __launch_bounds__(256) k_gemm_qkv(const float* __restrict__ x,
                                                  const float* __restrict__ Wqkv) {
    __shared__ float Ws[128 * 32];
    __shared__ float Xs[32 * 128];
    const int t  = blockIdx.x;
    const int rb = blockIdx.y;
    const int b  = blockIdx.z;
    const float* xb = x + ((size_t)b * CDIM * NSP);
    const float* W  = Wqkv + rb * 128 * 128;
    float* outp = g_qkv + ((size_t)b * 384 + rb * 128) * NSP + t * 128;

    const int tid = threadIdx.x;
    const int tx = tid & 15, ty = tid >> 4;

    float acc[8][8];
#pragma unroll
    for (int i = 0; i < 8; i++)
#pragma unroll
        for (int j = 0; j < 8; j++) acc[i][j] = 0.f;

    for (int kc = 0; kc < 4; kc++) {
#pragma unroll
        for (int i = 0; i < 4; i++) {
            int idx4 = tid + i * 256;
            int row = idx4 >> 3, k4 = (idx4 & 7) << 2;
            float4 w = *(const float4*)(W + row * 128 + kc * 32 + k4);
            *(float4*)(Ws + row * 32 + k4) = w;
            int kk = idx4 >> 5, c4 = (idx4 & 31) << 2;
            float4 v = *(const float4*)(xb + (size_t)(kc * 32 + kk) * NSP + t * 128 + c4);
            *(float4*)(Xs + kk * 128 + c4) = v;
        }
        __syncthreads();
#pragma unroll
        for (int kk = 0; kk < 32; kk++) {
            float a[8], bb[8];
#pragma unroll
            for (int i = 0; i < 8; i++) a[i] = Ws[(ty + 16 * i) * 32 + kk];
#pragma unroll
            for (int j = 0; j < 8; j++) bb[j] = Xs[kk * 128 + tx + 16 * j];
#pragma unroll
            for (int i = 0; i < 8; i++)
#pragma unroll
                for (int j = 0; j < 8; j++) acc[i][j] += a[i] * bb[j];
        }
        __syncthreads();
    }
#pragma unroll
    for (int i = 0; i < 8; i++)
#pragma unroll
        for (int j = 0; j < 8; j++)
            outp[(size_t)(ty + 16 * i) * NSP + tx + 16 * j] = acc[i][j];
}

// ---------------------------------------------------------------------------
// Kernel 2: context partials per (b, h, n-slab of 512):
//   Sp[d][e] = sum_n exp(k[d,n]) * v[e,n],   Zp[d] = sum_n exp(k[d,n])
// 256 threads: thread owns (d = tid>>3, 4 e's). Fixed-order sums (no atomics).
// grid = (4 heads, 8 slabs, 32 batches)
// ---------------------------------------------------------------------------
__global__ void __launch_bounds__(256) k_reduce_kv() {
    __shared__ float ks[32 * 129];
    __shared__ float vsT[128 * 33];
    const int h = blockIdx.x, p = blockIdx.y, b = blockIdx.z;
    const int tid = threadIdx.x;
    const int d = tid >> 3;
    const int e4 = (tid & 7) << 2;
    const float* kb = g_qkv + ((size_t)b * 384 + 128 + h * DH) * NSP + p * 512;
    const float* vb = g_qkv + ((size_t)b * 384 + 256 + h * DH) * NSP + p * 512;

    float acc0 = 0.f, acc1 = 0.f, acc2 = 0.f, acc3 = 0.f, zacc = 0.f;
    for (int ch = 0; ch < 4; ch++) {
        __syncthreads();
#pragma unroll
        for (int i = 0; i < 4; i++) {
            int idx4 = tid + i * 256;
            int r = idx4 >> 5, j4 = (idx4 & 31) << 2;
            float4 kv = *(const float4*)(kb + (size_t)r * NSP + ch * 128 + j4);
            ks[r * 129 + j4 + 0] = expf(kv.x);
            ks[r * 129 + j4 + 1] = expf(kv.y);
            ks[r * 129 + j4 + 2] = expf(kv.z);
            ks[r * 129 + j4 + 3] = expf(kv.w);
            float4 vv = *(const float4*)(vb + (size_t)r * NSP + ch * 128 + j4);
            vsT[(j4 + 0) * 33 + r] = vv.x;
            vsT[(j4 + 1) * 33 + r] = vv.y;
            vsT[(j4 + 2) * 33 + r] = vv.z;
            vsT[(j4 + 3) * 33 + r] = vv.w;
        }
        __syncthreads();
#pragma unroll 4
        for (int j = 0; j < 128; j++) {
            float kd = ks[d * 129 + j];
            zacc += kd;
            acc0 += kd * vsT[j * 33 + e4 + 0];
            acc1 += kd * vsT[j * 33 + e4 + 1];
            acc2 += kd * vsT[j * 33 + e4 + 2];
            acc3 += kd * vsT[j * 33 + e4 + 3];
        }
    }
    float* Sp = g_Sp + (((size_t)(b * HEADS + h) * 8 + p) << 10);
    Sp[d * 32 + e4 + 0] = acc0;
    Sp[d * 32 + e4 + 1] = acc1;
    Sp[d * 32 + e4 + 2] = acc2;
    Sp[d * 32 + e4 + 3] = acc3;
    if ((tid & 7) == 0) g_Zp[((b * HEADS + h) * 8 + p) * 32 + d] = zacc;
}

// ---------------------------------------------------------------------------
// Kernel 3: ctx = S/Z; M_b[o][h*32+d] = sum_e Wout[o][h*32+e] * ctx[h][d][e]
// grid = (32 batches), 256 threads. ~1 MFLOP each — tiny.
// ---------------------------------------------------------------------------
__global__ void __launch_bounds__(256) k_ctx_M(const float* __restrict__ Wout) {
    __shared__ float ctxs[4 * 32 * 33];
    __shared__ float zs[128];
    const int b = blockIdx.x;
    const int tid = threadIdx.x;
    if (tid < 128) {
        float z = 0.f;
#pragma unroll
        for (int p = 0; p < 8; p++)
            z += g_Zp[((b * HEADS + (tid >> 5)) * 8 + p) * 32 + (tid & 31)];
        zs[tid] = z;
    }
    __syncthreads();
    for (int idx = tid; idx < 4096; idx += 256) {
        int h = idx >> 10, d = (idx >> 5) & 31, e = idx & 31;
        float s = 0.f;
#pragma unroll
        for (int p = 0; p < 8; p++)
            s += g_Sp[(((size_t)(b * HEADS + h) * 8 + p) << 10) + d * 32 + e];
        ctxs[h * 1056 + d * 33 + e] = s / zs[h * 32 + d];
    }
    __syncthreads();
    float* Mb = g_M + (size_t)b * 16384;
    for (int pidx = tid; pidx < 16384; pidx += 256) {
        int o = pidx >> 7, hd = pidx & 127;
        int h = hd >> 5, d = hd & 31;
        const float* wrow = Wout + o * 128 + h * 32;
        const float* crow = ctxs + h * 1056 + d * 33;
        float s = 0.f;
#pragma unroll
        for (int e = 0; e < 32; e++) s += __ldg(wrow + e) * crow[e];
        Mb[pidx] = s;
    }
}

// ---------------------------------------------------------------------------
// Kernel 4: out = LayerNorm( M_b @ softmax_d(q) + bout ) -> NCHW
// Same 128x128 GEMM tile; K-chunk of 32 == one head, so softmax over d is
// applied in-smem on each loaded q chunk. LN (two-pass, biased var) fused.
// grid = (32 col tiles, 32 batches), 256 threads.
// ---------------------------------------------------------------------------
__global__ void __launch_bounds__(256) k_out(const float* __restrict__ bout,
                                             const float* __restrict__ lnw,
                                             const float* __restrict__ lnb,
                                             float* __restrict__ out) {
    __shared__ float Ms[128 * 32];
    __shared__ float Xs[32 * 128];
    __shared__ float red[4096];   // partials [16][128], colm @2048, colv @2176
    const int t = blockIdx.x;
    const int b = blockIdx.y;
    const int tid = threadIdx.x;
    const int tx = tid & 15, ty = tid >> 4;
    const float* Mb = g_M + (size_t)b * 16384;
    const float* qb = g_qkv + (size_t)b * 384 * NSP + t * 128;

    float acc[8][8];
#pragma unroll
    for (int i = 0; i < 8; i++)
#pragma unroll
        for (int j = 0; j < 8; j++) acc[i][j] = 0.f;

    for (int kc = 0; kc < 4; kc++) {   // kc == head index
#pragma unroll
        for (int i = 0; i < 4; i++) {
            int idx4 = tid + i * 256;
            int row = idx4 >> 3, k4 = (idx4 & 7) << 2;
            float4 w = *(const float4*)(Mb + row * 128 + kc * 32 + k4);
            *(float4*)(Ms + row * 32 + k4) = w;
            int kk = idx4 >> 5, c4 = (idx4 & 31) << 2;
            float4 v = *(const float4*)(qb + (size_t)(kc * 32 + kk) * NSP + c4);
            *(float4*)(Xs + kk * 128 + c4) = v;
        }
        __syncthreads();
        // softmax over the 32 rows of this head, per column
        if (tid < 128) {
            float s = 0.f;
#pragma unroll
            for (int kk = 0; kk < 32; kk++) {
                float e = expf(Xs[kk * 128 + tid]);
                Xs[kk * 128 + tid] = e;
                s += e;
            }
            float inv = 1.f / s;
#pragma unroll
            for (int kk = 0; kk < 32; kk++) Xs[kk * 128 + tid] *= inv;
        }
        __syncthreads();
#pragma unroll
        for (int kk = 0; kk < 32; kk++) {
            float a[8], bb[8];
#pragma unroll
            for (int i = 0; i < 8; i++) a[i] = Ms[(ty + 16 * i) * 32 + kk];
#pragma unroll
            for (int j = 0; j < 8; j++) bb[j] = Xs[kk * 128 + tx + 16 * j];
#pragma unroll
            for (int i = 0; i < 8; i++)
#pragma unroll
                for (int j = 0; j < 8; j++) acc[i][j] += a[i] * bb[j];
        }
        __syncthreads();
    }

    // + bias
#pragma unroll
    for (int i = 0; i < 8; i++) {
        float bo = __ldg(bout + ty + 16 * i);
#pragma unroll
        for (int j = 0; j < 8; j++) acc[i][j] += bo;
    }

    // LayerNorm over the 128 channels of each column (two-pass for stability)
#pragma unroll
    for (int j = 0; j < 8; j++) {
        float ps = 0.f;
#pragma unroll
        for (int i = 0; i < 8; i++) ps += acc[i][j];
        red[ty * 128 + tx + 16 * j] = ps;
    }
    __syncthreads();
    if (tid < 128) {
        float s = 0.f;
#pragma unroll
        for (int r = 0; r < 16; r++) s += red[r * 128 + tid];
        red[2048 + tid] = s * (1.f / 128.f);
    }
    __syncthreads();
#pragma unroll
    for (int j = 0; j < 8; j++) {
        float cm = red[2048 + tx + 16 * j];
        float ps = 0.f;
#pragma unroll
        for (int i = 0; i < 8; i++) {
            float d = acc[i][j] - cm;
            ps += d * d;
        }
        red[ty * 128 + tx + 16 * j] = ps;
    }
    __syncthreads();
    if (tid < 128) {
        float s = 0.f;
#pragma unroll
        for (int r = 0; r < 16; r++) s += red[r * 128 + tid];
        red[2176 + tid] = rsqrtf(s * (1.f / 128.f) + EPS);
    }
    __syncthreads();

#pragma unroll
    for (int i = 0; i < 8; i++) {
        int row = ty + 16 * i;
        float lw = __ldg(lnw + row);
        float lb = __ldg(lnb + row);
#pragma unroll
        for (int j = 0; j < 8; j++) {
            int col = tx + 16 * j;
            float v = (acc[i][j] - red[2048 + col]) * red[2176 + col] * lw + lb;
            out[((size_t)b * CDIM + row) * NSP + t * 128 + col] = v;
        }
    }
}

// ---------------------------------------------------------------------------
extern "C" void kernel_launch(void* const* d_in, const int* in_sizes, int n_in,
                              void* d_out, int out_size) {
    const float* x    = (const float*)d_in[0];
    const float* Wqkv = (const float*)d_in[1];
    const float* Wout = (const float*)d_in[2];
    const float* bout = (const float*)d_in[3];
    const float* lnw  = (const float*)d_in[4];
    const float* lnb  = (const float*)d_in[5];
    float* out = (float*)d_out;

    k_gemm_qkv<<<dim3(32, 3, B), 256>>>(x, Wqkv);
    k_reduce_kv<<<dim3(HEADS, 8, B), 256>>>();
    k_ctx_M<<<B, 256>>>(Wout);
    k_out<<<dim3(32, B), 256>>>(bout, lnw, lnb, out);
}

// round 2
// speedup vs baseline: 1.1044x; 1.1044x over previous
#include <cuda_runtime.h>
#include <math.h>

// Problem constants
#define B    32
#define CDIM 128
#define NSP  4096          // 64*64 spatial
#define HEADS 4
#define DH   32            // dim_head
#define EPS  1e-5f

typedef unsigned long long u64;

// Packed f32x2 helpers (FFMA2 — ptxas never auto-fuses; PTX only)
__device__ __forceinline__ u64 dup2(float x) {
    u64 r; asm("mov.b64 %0,{%1,%1};" : "=l"(r) : "f"(x)); return r;
}
__device__ __forceinline__ void ffma2(u64& d, u64 a, u64 b) {
    asm("fma.rn.f32x2 %0,%1,%2,%0;" : "+l"(d) : "l"(a), "l"(b));
}
__device__ __forceinline__ float2 unpk(u64 v) {
    float2 f; asm("mov.b64 {%0,%1},%2;" : "=f"(f.x), "=f"(f.y) : "l"(v)); return f;
}

// Scratch (static __device__ — no allocation allowed)
__device__ float g_qkv[(size_t)B * 384 * NSP];           // 201 MB staging
__device__ float g_Sp[(size_t)B * HEADS * 8 * DH * DH];  // context partials
__device__ float g_Zp[(size_t)B * HEADS * 8 * DH];       // Z partials
__device__ float g_M[(size_t)B * CDIM * CDIM];           // fused M_b = Wout∘ctx

// ---------------------------------------------------------------------------
// Kernel 1: qkv[b] = Wqkv(384x128) @ x[b](128x4096)   — FFMA2 inner loop
// 128x128 tile, 256 threads. Thread covers rows ty+16i (i<8) and column
// pairs (tx*2 + 32*j, +1) for j<4  → 8x8 floats as 8x4 f32x2 accumulators.
// grid = (32 col tiles, 3 row blocks, 32 batches)
// ---------------------------------------------------------------------------
__global__ void __launch_bounds__(256) k_gemm_qkv(const float* __restrict__ x,
                                                  const float* __restrict__ Wqkv) {
    __shared__ __align__(16) float Ws[128 * 32];
    __shared__ __align__(16) float Xs[32 * 128];
    const int t  = blockIdx.x;
    const int rb = blockIdx.y;
    const int b  = blockIdx.z;
    const float* xb = x + ((size_t)b * CDIM * NSP);
    const float* W  = Wqkv + rb * 128 * 128;
    float* outp = g_qkv + ((size_t)b * 384 + rb * 128) * NSP + t * 128;

    const int tid = threadIdx.x;
    const int tx = tid & 15, ty = tid >> 4;

    u64 acc[8][4];
#pragma unroll
    for (int i = 0; i < 8; i++)
#pragma unroll
        for (int j = 0; j < 4; j++) acc[i][j] = 0ull;

    for (int kc = 0; kc < 4; kc++) {
#pragma unroll
        for (int i = 0; i < 4; i++) {
            int idx4 = tid + i * 256;
            int row = idx4 >> 3, k4 = (idx4 & 7) << 2;
            float4 w = *(const float4*)(W + row * 128 + kc * 32 + k4);
            *(float4*)(Ws + row * 32 + k4) = w;
            int kk = idx4 >> 5, c4 = (idx4 & 31) << 2;
            float4 v = *(const float4*)(xb + (size_t)(kc * 32 + kk) * NSP + t * 128 + c4);
            *(float4*)(Xs + kk * 128 + c4) = v;
        }
        __syncthreads();
#pragma unroll
        for (int kk = 0; kk < 32; kk++) {
            u64 ar[8], bb[4];
#pragma unroll
            for (int i = 0; i < 8; i++) ar[i] = dup2(Ws[(ty + 16 * i) * 32 + kk]);
#pragma unroll
            for (int j = 0; j < 4; j++)
                bb[j] = *(const u64*)(Xs + kk * 128 + tx * 2 + 32 * j);
#pragma unroll
            for (int i = 0; i < 8; i++)
#pragma unroll
                for (int j = 0; j < 4; j++) ffma2(acc[i][j], ar[i], bb[j]);
        }
        __syncthreads();
    }
#pragma unroll
    for (int i = 0; i < 8; i++)
#pragma unroll
        for (int j = 0; j < 4; j++)
            *(float2*)(outp + (size_t)(ty + 16 * i) * NSP + tx * 2 + 32 * j) = unpk(acc[i][j]);
}

// ---------------------------------------------------------------------------
// Kernel 2: context partials per (b, h, n-slab of 512):
//   Sp[d][e] = sum_n exp(k[d,n]) * v[e,n],   Zp[d] = sum_n exp(k[d,n])
// FFMA2 inner loop, vsT padded to stride 36 floats (16B-aligned rows).
// grid = (4 heads, 8 slabs, 32 batches)
// ---------------------------------------------------------------------------
__global__ void __launch_bounds__(256) k_reduce_kv() {
    __shared__ __align__(16) float ks[32 * 129];
    __shared__ __align__(16) float vsT[128 * 36];
    const int h = blockIdx.x, p = blockIdx.y, b = blockIdx.z;
    const int tid = threadIdx.x;
    const int d = tid >> 3;
    const int e4 = (tid & 7) << 2;
    const float* kb = g_qkv + ((size_t)b * 384 + 128 + h * DH) * NSP + p * 512;
    const float* vb = g_qkv + ((size_t)b * 384 + 256 + h * DH) * NSP + p * 512;

    u64 a01 = 0ull, a23 = 0ull;
    float zacc = 0.f;
    for (int ch = 0; ch < 4; ch++) {
        __syncthreads();
#pragma unroll
        for (int i = 0; i < 4; i++) {
            int idx4 = tid + i * 256;
            int r = idx4 >> 5, j4 = (idx4 & 31) << 2;
            float4 kv = *(const float4*)(kb + (size_t)r * NSP + ch * 128 + j4);
            ks[r * 129 + j4 + 0] = expf(kv.x);
            ks[r * 129 + j4 + 1] = expf(kv.y);
            ks[r * 129 + j4 + 2] = expf(kv.z);
            ks[r * 129 + j4 + 3] = expf(kv.w);
            float4 vv = *(const float4*)(vb + (size_t)r * NSP + ch * 128 + j4);
            vsT[(j4 + 0) * 36 + r] = vv.x;
            vsT[(j4 + 1) * 36 + r] = vv.y;
            vsT[(j4 + 2) * 36 + r] = vv.z;
            vsT[(j4 + 3) * 36 + r] = vv.w;
        }
        __syncthreads();
#pragma unroll 4
        for (int j = 0; j < 128; j++) {
            float kd = ks[d * 129 + j];
            u64 k2 = dup2(kd);
            ulonglong2 vv = *(const ulonglong2*)(vsT + j * 36 + e4);
            ffma2(a01, k2, vv.x);
            ffma2(a23, k2, vv.y);
            zacc += kd;
        }
    }
    float* Sp = g_Sp + (((size_t)(b * HEADS + h) * 8 + p) << 10);
    float2 f01 = unpk(a01), f23 = unpk(a23);
    Sp[d * 32 + e4 + 0] = f01.x;
    Sp[d * 32 + e4 + 1] = f01.y;
    Sp[d * 32 + e4 + 2] = f23.x;
    Sp[d * 32 + e4 + 3] = f23.y;
    if ((tid & 7) == 0) g_Zp[((b * HEADS + h) * 8 + p) * 32 + d] = zacc;
}

// ---------------------------------------------------------------------------
// Kernel 3: ctx = S/Z; M_b[o][h*32+d] = sum_e Wout[o][h*32+e] * ctx[h][d][e]
// grid = (32 batches), 256 threads. Tiny.
// ---------------------------------------------------------------------------
__global__ void __launch_bounds__(256) k_ctx_M(const float* __restrict__ Wout) {
    __shared__ float ctxs[4 * 32 * 33];
    __shared__ float zs[128];
    const int b = blockIdx.x;
    const int tid = threadIdx.x;
    if (tid < 128) {
        float z = 0.f;
#pragma unroll
        for (int p = 0; p < 8; p++)
            z += g_Zp[((b * HEADS + (tid >> 5)) * 8 + p) * 32 + (tid & 31)];
        zs[tid] = z;
    }
    __syncthreads();
    for (int idx = tid; idx < 4096; idx += 256) {
        int h = idx >> 10, d = (idx >> 5) & 31, e = idx & 31;
        float s = 0.f;
#pragma unroll
        for (int p = 0; p < 8; p++)
            s += g_Sp[(((size_t)(b * HEADS + h) * 8 + p) << 10) + d * 32 + e];
        ctxs[h * 1056 + d * 33 + e] = s / zs[h * 32 + d];
    }
    __syncthreads();
    float* Mb = g_M + (size_t)b * 16384;
    for (int pidx = tid; pidx < 16384; pidx += 256) {
        int o = pidx >> 7, hd = pidx & 127;
        int h = hd >> 5, d = hd & 31;
        const float* wrow = Wout + o * 128 + h * 32;
        const float* crow = ctxs + h * 1056 + d * 33;
        float s = 0.f;
#pragma unroll
        for (int e = 0; e < 32; e++) s += __ldg(wrow + e) * crow[e];
        Mb[pidx] = s;
    }
}

// ---------------------------------------------------------------------------
// Kernel 4: out = LayerNorm( M_b @ softmax_d(q) + bout ) -> NCHW, FFMA2.
// Column mapping: thread owns column pairs (tx*2 + 32*j, +1) for j<4.
// grid = (32 col tiles, 32 batches), 256 threads.
// ---------------------------------------------------------------------------
__global__ void __launch_bounds__(256) k_out(const float* __restrict__ bout,
                                             const float* __restrict__ lnw,
                                             const float* __restrict__ lnb,
                                             float* __restrict__ out) {
    __shared__ __align__(16) float Ms[128 * 32];
    __shared__ __align__(16) float Xs[32 * 128];
    __shared__ float red[2304];   // partials [16][128], colm @2048, colv @2176
    const int t = blockIdx.x;
    const int b = blockIdx.y;
    const int tid = threadIdx.x;
    const int tx = tid & 15, ty = tid >> 4;
    const float* Mb = g_M + (size_t)b * 16384;
    const float* qb = g_qkv + (size_t)b * 384 * NSP + t * 128;

    u64 acc[8][4];
#pragma unroll
    for (int i = 0; i < 8; i++)
#pragma unroll
        for (int j = 0; j < 4; j++) acc[i][j] = 0ull;

    for (int kc = 0; kc < 4; kc++) {   // kc == head index
#pragma unroll
        for (int i = 0; i < 4; i++) {
            int idx4 = tid + i * 256;
            int row = idx4 >> 3, k4 = (idx4 & 7) << 2;
            float4 w = *(const float4*)(Mb + row * 128 + kc * 32 + k4);
            *(float4*)(Ms + row * 32 + k4) = w;
            int kk = idx4 >> 5, c4 = (idx4 & 31) << 2;
            float4 v = *(const float4*)(qb + (size_t)(kc * 32 + kk) * NSP + c4);
            *(float4*)(Xs + kk * 128 + c4) = v;
        }
        __syncthreads();
        // softmax over the 32 rows of this head, per column
        if (tid < 128) {
            float s = 0.f;
#pragma unroll
            for (int kk = 0; kk < 32; kk++) {
                float e = expf(Xs[kk * 128 + tid]);
                Xs[kk * 128 + tid] = e;
                s += e;
            }
            float inv = 1.f / s;
#pragma unroll
            for (int kk = 0; kk < 32; kk++) Xs[kk * 128 + tid] *= inv;
        }
        __syncthreads();
#pragma unroll
        for (int kk = 0; kk < 32; kk++) {
            u64 ar[8], bb[4];
#pragma unroll
            for (int i = 0; i < 8; i++) ar[i] = dup2(Ms[(ty + 16 * i) * 32 + kk]);
#pragma unroll
            for (int j = 0; j < 4; j++)
                bb[j] = *(const u64*)(Xs + kk * 128 + tx * 2 + 32 * j);
#pragma unroll
            for (int i = 0; i < 8; i++)
#pragma unroll
                for (int j = 0; j < 4; j++) ffma2(acc[i][j], ar[i], bb[j]);
        }
        __syncthreads();
    }

    // Unpack accumulators: facc[i][jj] is row ty+16i, col tx*2 + 32*(jj>>1) + (jj&1)
    float facc[8][8];
#pragma unroll
    for (int i = 0; i < 8; i++)
#pragma unroll
        for (int j = 0; j < 4; j++) {
            float2 f = unpk(acc[i][j]);
            facc[i][2 * j + 0] = f.x;
            facc[i][2 * j + 1] = f.y;
        }

    // + bias
#pragma unroll
    for (int i = 0; i < 8; i++) {
        float bo = __ldg(bout + ty + 16 * i);
#pragma unroll
        for (int jj = 0; jj < 8; jj++) facc[i][jj] += bo;
    }

    // LayerNorm over the 128 channels of each column (two-pass, biased var)
#pragma unroll
    for (int jj = 0; jj < 8; jj++) {
        int col = tx * 2 + 32 * (jj >> 1) + (jj & 1);
        float ps = 0.f;
#pragma unroll
        for (int i = 0; i < 8; i++) ps += facc[i][jj];
        red[ty * 128 + col] = ps;
    }
    __syncthreads();
    if (tid < 128) {
        float s = 0.f;
#pragma unroll
        for (int r = 0; r < 16; r++) s += red[r * 128 + tid];
        red[2048 + tid] = s * (1.f / 128.f);
    }
    __syncthreads();
#pragma unroll
    for (int jj = 0; jj < 8; jj++) {
        int col = tx * 2 + 32 * (jj >> 1) + (jj & 1);
        float cm = red[2048 + col];
        float ps = 0.f;
#pragma unroll
        for (int i = 0; i < 8; i++) {
            float dd = facc[i][jj] - cm;
            ps += dd * dd;
        }
        red[ty * 128 + col] = ps;
    }
    __syncthreads();
    if (tid < 128) {
        float s = 0.f;
#pragma unroll
        for (int r = 0; r < 16; r++) s += red[r * 128 + tid];
        red[2176 + tid] = rsqrtf(s * (1.f / 128.f) + EPS);
    }
    __syncthreads();

#pragma unroll
    for (int i = 0; i < 8; i++) {
        int row = ty + 16 * i;
        float lw = __ldg(lnw + row);
        float lb = __ldg(lnb + row);
#pragma unroll
        for (int j = 0; j < 4; j++) {
            int col = tx * 2 + 32 * j;
            float2 o2;
            o2.x = (facc[i][2 * j + 0] - red[2048 + col + 0]) * red[2176 + col + 0] * lw + lb;
            o2.y = (facc[i][2 * j + 1] - red[2048 + col + 1]) * red[2176 + col + 1] * lw + lb;
            *(float2*)(out + ((size_t)b * CDIM + row) * NSP + t * 128 + col) = o2;
        }
    }
}

// ---------------------------------------------------------------------------
extern "C" void kernel_launch(void* const* d_in, const int* in_sizes, int n_in,
                              void* d_out, int out_size) {
    const float* x    = (const float*)d_in[0];
    const float* Wqkv = (const float*)d_in[1];
    const float* Wout = (const float*)d_in[2];
    const float* bout = (const float*)d_in[3];
    const float* lnw  = (const float*)d_in[4];
    const float* lnb  = (const float*)d_in[5];
    float* out = (float*)d_out;

    k_gemm_qkv<<<dim3(32, 3, B), 256>>>(x, Wqkv);
    k_reduce_kv<<<dim3(HEADS, 8, B), 256>>>();
    k_ctx_M<<<B, 256>>>(Wout);
    k_out<<<dim3(32, B), 256>>>(bout, lnw, lnb, out);
}

// round 5
// speedup vs baseline: 1.5330x; 1.3881x over previous
#include <cuda_runtime.h>
#include <cuda_bf16.h>
#include <math.h>

// Problem constants
#define B    32
#define CDIM 128
#define NSP  4096
#define HEADS 4
#define DH   32
#define EPS  1e-5f

typedef unsigned long long u64;
typedef unsigned int u32;

// ---------------- packed f32x2 helpers ----------------
__device__ __forceinline__ u64 dup2(float x) {
    u64 r; asm("mov.b64 %0,{%1,%1};" : "=l"(r) : "f"(x)); return r;
}
__device__ __forceinline__ void ffma2(u64& d, u64 a, u64 b) {
    asm("fma.rn.f32x2 %0,%1,%2,%0;" : "+l"(d) : "l"(a), "l"(b));
}
__device__ __forceinline__ float2 unpk(u64 v) {
    float2 f; asm("mov.b64 {%0,%1},%2;" : "=f"(f.x), "=f"(f.y) : "l"(v)); return f;
}

// ---------------- FFMA-only exp (no MUFU): exp(x)=2^(x*log2e) ----------------
// magic-round + deg-4 poly on f in [-0.5,0.5] + exponent bit insert. rel err <5e-5.
__device__ __forceinline__ float exp_poly(float x) {
    float y = x * 1.4426950408889634f;
    float z = y + 12582912.0f;              // 1.5*2^23
    int   zb = __float_as_int(z);
    float n = z - 12582912.0f;
    float f = y - n;
    float p = 0.0096180f;
    p = fmaf(p, f, 0.0555041f);
    p = fmaf(p, f, 0.2402265f);
    p = fmaf(p, f, 0.6931472f);
    p = fmaf(p, f, 1.0f);
    return __int_as_float(__float_as_int(p) + (zb << 23));
}

// ---------------- mma.sync / ldmatrix wrappers ----------------
__device__ __forceinline__ void ldm4(u32* d, u32 addr) {
    asm volatile("ldmatrix.sync.aligned.m8n8.x4.shared.b16 {%0,%1,%2,%3},[%4];"
                 : "=r"(d[0]), "=r"(d[1]), "=r"(d[2]), "=r"(d[3]) : "r"(addr));
}
__device__ __forceinline__ void mma16816(float* c, const u32* a, u32 b0, u32 b1) {
    asm volatile("mma.sync.aligned.m16n8k16.row.col.f32.bf16.bf16.f32 "
                 "{%0,%1,%2,%3},{%4,%5,%6,%7},{%8,%9},{%0,%1,%2,%3};"
                 : "+f"(c[0]), "+f"(c[1]), "+f"(c[2]), "+f"(c[3])
                 : "r"(a[0]), "r"(a[1]), "r"(a[2]), "r"(a[3]), "r"(b0), "r"(b1));
}

// ---------------- scratch ----------------
__device__ float g_qkv[(size_t)B * 384 * NSP];
__device__ float g_Sp[(size_t)B * HEADS * 8 * DH * DH];
__device__ float g_Zp[(size_t)B * HEADS * 8 * DH];
__device__ float g_M[(size_t)B * CDIM * CDIM];
__device__ __align__(16) unsigned short g_Wh[384 * 128];   // Wqkv bf16 hi
__device__ __align__(16) unsigned short g_Wl[384 * 128];   // Wqkv bf16 lo

// ---------------------------------------------------------------------------
// Kernel 0: split Wqkv into bf16 hi/lo (tiny)
// ---------------------------------------------------------------------------
__global__ void k_splitW(const float* __restrict__ W) {
    for (int i = blockIdx.x * blockDim.x + threadIdx.x; i < 384 * 128;
         i += gridDim.x * blockDim.x) {
        float w = W[i];
        __nv_bfloat16 hb = __float2bfloat16(w);
        float hf = __bfloat162float(hb);
        __nv_bfloat16 lb = __float2bfloat16(w - hf);
        g_Wh[i] = __bfloat16_as_ushort(hb);
        g_Wl[i] = __bfloat16_as_ushort(lb);
    }
}

// ---------------------------------------------------------------------------
// Kernel 1: qkv[b] = Wqkv(384x128) @ x[b](128x4096) via split-bf16 mma.sync
// grid=(32 n-tiles, 32 batches), 256 threads (8 warps: 4 m x 2 n).
// smem: Bh/Bl = x-tile bf16 [n=128][k=128] stride 272B;
//       fp32 stage [k=128][132]  (132-stride => 528B rows, 16B-aligned float4)
//       overlaid later by Ah/Al [m=128][k=128].
// ---------------------------------------------------------------------------
#define SMEM_K1 139264
__global__ void __launch_bounds__(256) k_gemm_qkv(const float* __restrict__ x) {
    extern __shared__ char sm[];
    const u32 sbase = (u32)__cvta_generic_to_shared(sm);
    const u32 oBh = 0, oBl = 34816, oStage = 69632, oAh = 69632, oAl = 104448;
    float* stage = (float*)(sm + oStage);
    const int t = blockIdx.x, b = blockIdx.y;
    const int tid = threadIdx.x;
    const float* xb = x + (size_t)b * CDIM * NSP + t * 128;

    // phase 1: x tile -> fp32 stage [k][132]
#pragma unroll
    for (int it = 0; it < 16; it++) {
        int u = tid + it * 256;
        int k = u >> 5, nc = (u & 31) << 2;
        float4 v = *(const float4*)(xb + (size_t)k * NSP + nc);
        *(float4*)(stage + k * 132 + nc) = v;
    }
    __syncthreads();

    // phase 2: convert to bf16 hi/lo in [n][k] layout (transpose via stage)
#pragma unroll
    for (int it = 0; it < 8; it++) {
        int v = tid + it * 256;
        int n = v & 127, k8 = v >> 7;
        float f[8];
#pragma unroll
        for (int j = 0; j < 8; j++) f[j] = stage[(k8 * 8 + j) * 132 + n];
        u32 hw[4], lw[4];
#pragma unroll
        for (int jj = 0; jj < 4; jj++) {
            u32 h;
            asm("cvt.rn.bf16x2.f32 %0,%1,%2;" : "=r"(h) : "f"(f[2 * jj + 1]), "f"(f[2 * jj]));
            float hlo = __int_as_float((int)(h << 16));
            float hhi = __int_as_float((int)(h & 0xFFFF0000u));
            float rlo = f[2 * jj] - hlo, rhi = f[2 * jj + 1] - hhi;
            u32 lo;
            asm("cvt.rn.bf16x2.f32 %0,%1,%2;" : "=r"(lo) : "f"(rhi), "f"(rlo));
            hw[jj] = h; lw[jj] = lo;
        }
        u32 off = n * 272 + k8 * 16;
        *(uint4*)(sm + oBh + off) = make_uint4(hw[0], hw[1], hw[2], hw[3]);
        *(uint4*)(sm + oBl + off) = make_uint4(lw[0], lw[1], lw[2], lw[3]);
    }
    __syncthreads();

    const int l = tid & 31, wid = tid >> 5;
    const int wm = (wid & 3) * 32;   // warp m offset
    const int nh = (wid >> 2) * 64;  // warp n offset
    // ldmatrix per-lane byte offsets (add tile/kc offsets per use)
    const u32 aoff = (u32)((wm + (l & 15)) * 272 + (l >> 4) * 16);
    const u32 boff = (u32)((nh + (l & 7) + ((l >> 4) << 3)) * 272 + (((l >> 3) & 1) << 4));

    for (int rb = 0; rb < 3; rb++) {
        // load A (pre-split W) rows rb*128..+127
        {
            const uint4* gh = (const uint4*)(g_Wh + (size_t)rb * 128 * 128);
            const uint4* gl = (const uint4*)(g_Wl + (size_t)rb * 128 * 128);
#pragma unroll
            for (int it = 0; it < 8; it++) {
                int u = tid + it * 256;
                int r = u >> 4, c = u & 15;
                u32 off = r * 272 + c * 16;
                *(uint4*)(sm + oAh + off) = gh[r * 16 + c];
                *(uint4*)(sm + oAl + off) = gl[r * 16 + c];
            }
        }
        __syncthreads();

        float acc[2][8][4];
#pragma unroll
        for (int mt = 0; mt < 2; mt++)
#pragma unroll
            for (int nt = 0; nt < 8; nt++)
#pragma unroll
                for (int q = 0; q < 4; q++) acc[mt][nt][q] = 0.f;

#pragma unroll
        for (int kc = 0; kc < 8; kc++) {
            u32 ah[2][4], al_[2][4], bhf[4][4], blf[4][4];
#pragma unroll
            for (int mt = 0; mt < 2; mt++) {
                u32 o = aoff + mt * (16 * 272) + kc * 32;
                ldm4(ah[mt],  sbase + oAh + o);
                ldm4(al_[mt], sbase + oAl + o);
            }
#pragma unroll
            for (int p = 0; p < 4; p++) {
                u32 o = boff + p * (16 * 272) + kc * 32;
                ldm4(bhf[p], sbase + oBh + o);
                ldm4(blf[p], sbase + oBl + o);
            }
#pragma unroll
            for (int mt = 0; mt < 2; mt++)
#pragma unroll
                for (int nt = 0; nt < 8; nt++) {
                    int p = nt >> 1, q = (nt & 1) * 2;
                    mma16816(acc[mt][nt], ah[mt],  bhf[p][q], bhf[p][q + 1]);
                    mma16816(acc[mt][nt], al_[mt], bhf[p][q], bhf[p][q + 1]);
                    mma16816(acc[mt][nt], ah[mt],  blf[p][q], blf[p][q + 1]);
                }
        }

        float* outp = g_qkv + ((size_t)b * 384 + rb * 128) * NSP + t * 128;
#pragma unroll
        for (int mt = 0; mt < 2; mt++)
#pragma unroll
            for (int rh = 0; rh < 2; rh++) {
                int row = wm + mt * 16 + (l >> 2) + rh * 8;
#pragma unroll
                for (int nt = 0; nt < 8; nt++) {
                    int col = nh + nt * 8 + (l & 3) * 2;
                    float2 v2 = make_float2(acc[mt][nt][rh * 2], acc[mt][nt][rh * 2 + 1]);
                    *(float2*)(outp + (size_t)row * NSP + col) = v2;
                }
            }
        __syncthreads();
    }
}

// ---------------------------------------------------------------------------
// Kernel 2: context partials: Sp[d][e]=sum_n exp(k[d,n])*v[e,n], Zp[d]=sum exp
// Hybrid exp: warp-uniform split poly/MUFU (p~7/16).
// ---------------------------------------------------------------------------
__global__ void __launch_bounds__(256) k_reduce_kv() {
    __shared__ __align__(16) float ks[32 * 129];
    __shared__ __align__(16) float vsT[128 * 36];
    const int h = blockIdx.x, p = blockIdx.y, b = blockIdx.z;
    const int tid = threadIdx.x;
    const int d = tid >> 3;
    const int e4 = (tid & 7) << 2;
    const float* kb = g_qkv + ((size_t)b * 384 + 128 + h * DH) * NSP + p * 512;
    const float* vb = g_qkv + ((size_t)b * 384 + 256 + h * DH) * NSP + p * 512;

    u64 a01 = 0ull, a23 = 0ull;
    float zacc = 0.f;
    for (int ch = 0; ch < 4; ch++) {
        __syncthreads();
#pragma unroll
        for (int i = 0; i < 4; i++) {
            int idx4 = tid + i * 256;
            int r = idx4 >> 5, j4 = (idx4 & 31) << 2;
            float4 kv = *(const float4*)(kb + (size_t)r * NSP + ch * 128 + j4);
            if ((r & 15) < 7) {          // warp-uniform: FFMA-poly path
                ks[r * 129 + j4 + 0] = exp_poly(kv.x);
                ks[r * 129 + j4 + 1] = exp_poly(kv.y);
                ks[r * 129 + j4 + 2] = exp_poly(kv.z);
                ks[r * 129 + j4 + 3] = exp_poly(kv.w);
            } else {                      // MUFU path
                ks[r * 129 + j4 + 0] = __expf(kv.x);
                ks[r * 129 + j4 + 1] = __expf(kv.y);
                ks[r * 129 + j4 + 2] = __expf(kv.z);
                ks[r * 129 + j4 + 3] = __expf(kv.w);
            }
            float4 vv = *(const float4*)(vb + (size_t)r * NSP + ch * 128 + j4);
            vsT[(j4 + 0) * 36 + r] = vv.x;
            vsT[(j4 + 1) * 36 + r] = vv.y;
            vsT[(j4 + 2) * 36 + r] = vv.z;
            vsT[(j4 + 3) * 36 + r] = vv.w;
        }
        __syncthreads();
#pragma unroll 4
        for (int j = 0; j < 128; j++) {
            float kd = ks[d * 129 + j];
            u64 k2 = dup2(kd);
            ulonglong2 vv = *(const ulonglong2*)(vsT + j * 36 + e4);
            ffma2(a01, k2, vv.x);
            ffma2(a23, k2, vv.y);
            zacc += kd;
        }
    }
    float* Sp = g_Sp + (((size_t)(b * HEADS + h) * 8 + p) << 10);
    float2 f01 = unpk(a01), f23 = unpk(a23);
    Sp[d * 32 + e4 + 0] = f01.x;
    Sp[d * 32 + e4 + 1] = f01.y;
    Sp[d * 32 + e4 + 2] = f23.x;
    Sp[d * 32 + e4 + 3] = f23.y;
    if ((tid & 7) == 0) g_Zp[((b * HEADS + h) * 8 + p) * 32 + d] = zacc;
}

// ---------------------------------------------------------------------------
// Kernel 3: ctx = S/Z; M_b[o][h*32+d] = sum_e Wout[o][h*32+e]*ctx[h][d][e]
// ---------------------------------------------------------------------------
__global__ void __launch_bounds__(256) k_ctx_M(const float* __restrict__ Wout) {
    __shared__ float ctxs[4 * 32 * 33];
    __shared__ float zs[128];
    const int b = blockIdx.x;
    const int tid = threadIdx.x;
    if (tid < 128) {
        float z = 0.f;
#pragma unroll
        for (int p = 0; p < 8; p++)
            z += g_Zp[((b * HEADS + (tid >> 5)) * 8 + p) * 32 + (tid & 31)];
        zs[tid] = z;
    }
    __syncthreads();
    for (int idx = tid; idx < 4096; idx += 256) {
        int h = idx >> 10, d = (idx >> 5) & 31, e = idx & 31;
        float s = 0.f;
#pragma unroll
        for (int p = 0; p < 8; p++)
            s += g_Sp[(((size_t)(b * HEADS + h) * 8 + p) << 10) + d * 32 + e];
        ctxs[h * 1056 + d * 33 + e] = s / zs[h * 32 + d];
    }
    __syncthreads();
    float* Mb = g_M + (size_t)b * 16384;
    for (int pidx = tid; pidx < 16384; pidx += 256) {
        int o = pidx >> 7, hd = pidx & 127;
        int h = hd >> 5, d = hd & 31;
        const float* wrow = Wout + o * 128 + h * 32;
        const float* crow = ctxs + h * 1056 + d * 33;
        float s = 0.f;
#pragma unroll
        for (int e = 0; e < 32; e++) s += __ldg(wrow + e) * crow[e];
        Mb[pidx] = s;
    }
}

// ---------------------------------------------------------------------------
// Kernel 4: out = LayerNorm( M_b @ softmax_d(q) + bout ), FFMA2 GEMM,
// hybrid exp (p=3/16 poly, compile-time uniform per kk row).
// ---------------------------------------------------------------------------
__global__ void __launch_bounds__(256) k_out(const float* __restrict__ bout,
                                             const float* __restrict__ lnw,
                                             const float* __restrict__ lnb,
                                             float* __restrict__ out) {
    __shared__ __align__(16) float Ms[128 * 32];
    __shared__ __align__(16) float Xs[32 * 128];
    __shared__ float red[2304];
    const int t = blockIdx.x;
    const int b = blockIdx.y;
    const int tid = threadIdx.x;
    const int tx = tid & 15, ty = tid >> 4;
    const float* Mb = g_M + (size_t)b * 16384;
    const float* qb = g_qkv + (size_t)b * 384 * NSP + t * 128;

    u64 acc[8][4];
#pragma unroll
    for (int i = 0; i < 8; i++)
#pragma unroll
        for (int j = 0; j < 4; j++) acc[i][j] = 0ull;

    for (int kc = 0; kc < 4; kc++) {
#pragma unroll
        for (int i = 0; i < 4; i++) {
            int idx4 = tid + i * 256;
            int row = idx4 >> 3, k4 = (idx4 & 7) << 2;
            float4 w = *(const float4*)(Mb + row * 128 + kc * 32 + k4);
            *(float4*)(Ms + row * 32 + k4) = w;
            int kk = idx4 >> 5, c4 = (idx4 & 31) << 2;
            float4 v = *(const float4*)(qb + (size_t)(kc * 32 + kk) * NSP + c4);
            *(float4*)(Xs + kk * 128 + c4) = v;
        }
        __syncthreads();
        if (tid < 128) {
            float s = 0.f;
#pragma unroll
            for (int kk = 0; kk < 32; kk++) {
                float xv = Xs[kk * 128 + tid];
                float e = ((kk & 15) < 3) ? exp_poly(xv) : __expf(xv);
                Xs[kk * 128 + tid] = e;
                s += e;
            }
            float inv = 1.f / s;
#pragma unroll
            for (int kk = 0; kk < 32; kk++) Xs[kk * 128 + tid] *= inv;
        }
        __syncthreads();
#pragma unroll
        for (int kk = 0; kk < 32; kk++) {
            u64 ar[8], bb[4];
#pragma unroll
            for (int i = 0; i < 8; i++) ar[i] = dup2(Ms[(ty + 16 * i) * 32 + kk]);
#pragma unroll
            for (int j = 0; j < 4; j++)
                bb[j] = *(const u64*)(Xs + kk * 128 + tx * 2 + 32 * j);
#pragma unroll
            for (int i = 0; i < 8; i++)
#pragma unroll
                for (int j = 0; j < 4; j++) ffma2(acc[i][j], ar[i], bb[j]);
        }
        __syncthreads();
    }

    float facc[8][8];
#pragma unroll
    for (int i = 0; i < 8; i++)
#pragma unroll
        for (int j = 0; j < 4; j++) {
            float2 f = unpk(acc[i][j]);
            facc[i][2 * j + 0] = f.x;
            facc[i][2 * j + 1] = f.y;
        }

#pragma unroll
    for (int i = 0; i < 8; i++) {
        float bo = __ldg(bout + ty + 16 * i);
#pragma unroll
        for (int jj = 0; jj < 8; jj++) facc[i][jj] += bo;
    }

#pragma unroll
    for (int jj = 0; jj < 8; jj++) {
        int col = tx * 2 + 32 * (jj >> 1) + (jj & 1);
        float ps = 0.f;
#pragma unroll
        for (int i = 0; i < 8; i++) ps += facc[i][jj];
        red[ty * 128 + col] = ps;
    }
    __syncthreads();
    if (tid < 128) {
        float s = 0.f;
#pragma unroll
        for (int r = 0; r < 16; r++) s += red[r * 128 + tid];
        red[2048 + tid] = s * (1.f / 128.f);
    }
    __syncthreads();
#pragma unroll
    for (int jj = 0; jj < 8; jj++) {
        int col = tx * 2 + 32 * (jj >> 1) + (jj & 1);
        float cm = red[2048 + col];
        float ps = 0.f;
#pragma unroll
        for (int i = 0; i < 8; i++) {
            float dd = facc[i][jj] - cm;
            ps += dd * dd;
        }
        red[ty * 128 + col] = ps;
    }
    __syncthreads();
    if (tid < 128) {
        float s = 0.f;
#pragma unroll
        for (int r = 0; r < 16; r++) s += red[r * 128 + tid];
        red[2176 + tid] = rsqrtf(s * (1.f / 128.f) + EPS);
    }
    __syncthreads();

#pragma unroll
    for (int i = 0; i < 8; i++) {
        int row = ty + 16 * i;
        float lw = __ldg(lnw + row);
        float lb = __ldg(lnb + row);
#pragma unroll
        for (int j = 0; j < 4; j++) {
            int col = tx * 2 + 32 * j;
            float2 o2;
            o2.x = (facc[i][2 * j + 0] - red[2048 + col + 0]) * red[2176 + col + 0] * lw + lb;
            o2.y = (facc[i][2 * j + 1] - red[2048 + col + 1]) * red[2176 + col + 1] * lw + lb;
            *(float2*)(out + ((size_t)b * CDIM + row) * NSP + t * 128 + col) = o2;
        }
    }
}

// ---------------------------------------------------------------------------
extern "C" void kernel_launch(void* const* d_in, const int* in_sizes, int n_in,
                              void* d_out, int out_size) {
    const float* x    = (const float*)d_in[0];
    const float* Wqkv = (const float*)d_in[1];
    const float* Wout = (const float*)d_in[2];
    const float* bout = (const float*)d_in[3];
    const float* lnw  = (const float*)d_in[4];
    const float* lnb  = (const float*)d_in[5];
    float* out = (float*)d_out;

    cudaFuncSetAttribute(k_gemm_qkv, cudaFuncAttributeMaxDynamicSharedMemorySize, SMEM_K1);

    k_splitW<<<48, 256>>>(Wqkv);
    k_gemm_qkv<<<dim3(32, B), 256, SMEM_K1>>>(x);
    k_reduce_kv<<<dim3(HEADS, 8, B), 256>>>();
    k_ctx_M<<<B, 256>>>(Wout);
    k_out<<<dim3(32, B), 256>>>(bout, lnw, lnb, out);
}

// round 6
// speedup vs baseline: 1.8923x; 1.2344x over previous
#include <cuda_runtime.h>
#include <cuda_bf16.h>
#include <math.h>

#define B    32
#define CDIM 128
#define NSP  4096
#define HEADS 4
#define DH   32
#define EPS  1e-5f

typedef unsigned long long u64;
typedef unsigned int u32;

// ---------------- packed f32x2 helpers ----------------
__device__ __forceinline__ u64 dup2(float x) {
    u64 r; asm("mov.b64 %0,{%1,%1};" : "=l"(r) : "f"(x)); return r;
}
__device__ __forceinline__ void ffma2(u64& d, u64 a, u64 b) {
    asm("fma.rn.f32x2 %0,%1,%2,%0;" : "+l"(d) : "l"(a), "l"(b));
}
__device__ __forceinline__ float2 unpk(u64 v) {
    float2 f; asm("mov.b64 {%0,%1},%2;" : "=f"(f.x), "=f"(f.y) : "l"(v)); return f;
}

// ---------------- FFMA-only exp ----------------
__device__ __forceinline__ float exp_poly(float x) {
    float y = x * 1.4426950408889634f;
    float z = y + 12582912.0f;
    int   zb = __float_as_int(z);
    float n = z - 12582912.0f;
    float f = y - n;
    float p = 0.0096180f;
    p = fmaf(p, f, 0.0555041f);
    p = fmaf(p, f, 0.2402265f);
    p = fmaf(p, f, 0.6931472f);
    p = fmaf(p, f, 1.0f);
    return __int_as_float(__float_as_int(p) + (zb << 23));
}

// ---------------- mma.sync / ldmatrix wrappers ----------------
__device__ __forceinline__ void ldm4(u32* d, u32 addr) {
    asm volatile("ldmatrix.sync.aligned.m8n8.x4.shared.b16 {%0,%1,%2,%3},[%4];"
                 : "=r"(d[0]), "=r"(d[1]), "=r"(d[2]), "=r"(d[3]) : "r"(addr));
}
__device__ __forceinline__ void mma16816(float* c, const u32* a, u32 b0, u32 b1) {
    asm volatile("mma.sync.aligned.m16n8k16.row.col.f32.bf16.bf16.f32 "
                 "{%0,%1,%2,%3},{%4,%5,%6,%7},{%8,%9},{%0,%1,%2,%3};"
                 : "+f"(c[0]), "+f"(c[1]), "+f"(c[2]), "+f"(c[3])
                 : "r"(a[0]), "r"(a[1]), "r"(a[2]), "r"(a[3]), "r"(b0), "r"(b1));
}

// ---------------- scratch ----------------
__device__ float g_qkv[(size_t)B * 384 * NSP];
__device__ float g_Sp[(size_t)B * HEADS * 8 * DH * DH];
__device__ float g_Zp[(size_t)B * HEADS * 8 * DH];
__device__ __align__(16) unsigned short g_Wh[384 * 128];
__device__ __align__(16) unsigned short g_Wl[384 * 128];
__device__ __align__(16) unsigned short g_Mbh[(size_t)B * 16384];  // M_b bf16 hi
__device__ __align__(16) unsigned short g_Mbl[(size_t)B * 16384];  // M_b bf16 lo

// ---------------------------------------------------------------------------
// Kernel 0: split Wqkv into bf16 hi/lo
// ---------------------------------------------------------------------------
__global__ void k_splitW(const float* __restrict__ W) {
    for (int i = blockIdx.x * blockDim.x + threadIdx.x; i < 384 * 128;
         i += gridDim.x * blockDim.x) {
        float w = W[i];
        __nv_bfloat16 hb = __float2bfloat16(w);
        float hf = __bfloat162float(hb);
        __nv_bfloat16 lb = __float2bfloat16(w - hf);
        g_Wh[i] = __bfloat16_as_ushort(hb);
        g_Wl[i] = __bfloat16_as_ushort(lb);
    }
}

// ---------------------------------------------------------------------------
// Kernel 1: qkv = Wqkv @ x via split-bf16 mma.sync (unchanged from R5)
// ---------------------------------------------------------------------------
#define SMEM_K1 139264
__global__ void __launch_bounds__(256) k_gemm_qkv(const float* __restrict__ x) {
    extern __shared__ char sm[];
    const u32 sbase = (u32)__cvta_generic_to_shared(sm);
    const u32 oBh = 0, oBl = 34816, oStage = 69632, oAh = 69632, oAl = 104448;
    float* stage = (float*)(sm + oStage);
    const int t = blockIdx.x, b = blockIdx.y;
    const int tid = threadIdx.x;
    const float* xb = x + (size_t)b * CDIM * NSP + t * 128;

#pragma unroll
    for (int it = 0; it < 16; it++) {
        int u = tid + it * 256;
        int k = u >> 5, nc = (u & 31) << 2;
        float4 v = *(const float4*)(xb + (size_t)k * NSP + nc);
        *(float4*)(stage + k * 132 + nc) = v;
    }
    __syncthreads();

#pragma unroll
    for (int it = 0; it < 8; it++) {
        int v = tid + it * 256;
        int n = v & 127, k8 = v >> 7;
        float f[8];
#pragma unroll
        for (int j = 0; j < 8; j++) f[j] = stage[(k8 * 8 + j) * 132 + n];
        u32 hw[4], lw[4];
#pragma unroll
        for (int jj = 0; jj < 4; jj++) {
            u32 h;
            asm("cvt.rn.bf16x2.f32 %0,%1,%2;" : "=r"(h) : "f"(f[2 * jj + 1]), "f"(f[2 * jj]));
            float hlo = __int_as_float((int)(h << 16));
            float hhi = __int_as_float((int)(h & 0xFFFF0000u));
            float rlo = f[2 * jj] - hlo, rhi = f[2 * jj + 1] - hhi;
            u32 lo;
            asm("cvt.rn.bf16x2.f32 %0,%1,%2;" : "=r"(lo) : "f"(rhi), "f"(rlo));
            hw[jj] = h; lw[jj] = lo;
        }
        u32 off = n * 272 + k8 * 16;
        *(uint4*)(sm + oBh + off) = make_uint4(hw[0], hw[1], hw[2], hw[3]);
        *(uint4*)(sm + oBl + off) = make_uint4(lw[0], lw[1], lw[2], lw[3]);
    }
    __syncthreads();

    const int l = tid & 31, wid = tid >> 5;
    const int wm = (wid & 3) * 32;
    const int nh = (wid >> 2) * 64;
    const u32 aoff = (u32)((wm + (l & 15)) * 272 + (l >> 4) * 16);
    const u32 boff = (u32)((nh + (l & 7) + ((l >> 4) << 3)) * 272 + (((l >> 3) & 1) << 4));

    for (int rb = 0; rb < 3; rb++) {
        {
            const uint4* gh = (const uint4*)(g_Wh + (size_t)rb * 128 * 128);
            const uint4* gl = (const uint4*)(g_Wl + (size_t)rb * 128 * 128);
#pragma unroll
            for (int it = 0; it < 8; it++) {
                int u = tid + it * 256;
                int r = u >> 4, c = u & 15;
                u32 off = r * 272 + c * 16;
                *(uint4*)(sm + oAh + off) = gh[r * 16 + c];
                *(uint4*)(sm + oAl + off) = gl[r * 16 + c];
            }
        }
        __syncthreads();

        float acc[2][8][4];
#pragma unroll
        for (int mt = 0; mt < 2; mt++)
#pragma unroll
            for (int nt = 0; nt < 8; nt++)
#pragma unroll
                for (int q = 0; q < 4; q++) acc[mt][nt][q] = 0.f;

#pragma unroll
        for (int kc = 0; kc < 8; kc++) {
            u32 ah[2][4], al_[2][4], bhf[4][4], blf[4][4];
#pragma unroll
            for (int mt = 0; mt < 2; mt++) {
                u32 o = aoff + mt * (16 * 272) + kc * 32;
                ldm4(ah[mt],  sbase + oAh + o);
                ldm4(al_[mt], sbase + oAl + o);
            }
#pragma unroll
            for (int p = 0; p < 4; p++) {
                u32 o = boff + p * (16 * 272) + kc * 32;
                ldm4(bhf[p], sbase + oBh + o);
                ldm4(blf[p], sbase + oBl + o);
            }
#pragma unroll
            for (int mt = 0; mt < 2; mt++)
#pragma unroll
                for (int nt = 0; nt < 8; nt++) {
                    int p = nt >> 1, q = (nt & 1) * 2;
                    mma16816(acc[mt][nt], ah[mt],  bhf[p][q], bhf[p][q + 1]);
                    mma16816(acc[mt][nt], al_[mt], bhf[p][q], bhf[p][q + 1]);
                    mma16816(acc[mt][nt], ah[mt],  blf[p][q], blf[p][q + 1]);
                }
        }

        float* outp = g_qkv + ((size_t)b * 384 + rb * 128) * NSP + t * 128;
#pragma unroll
        for (int mt = 0; mt < 2; mt++)
#pragma unroll
            for (int rh = 0; rh < 2; rh++) {
                int row = wm + mt * 16 + (l >> 2) + rh * 8;
#pragma unroll
                for (int nt = 0; nt < 8; nt++) {
                    int col = nh + nt * 8 + (l & 3) * 2;
                    float2 v2 = make_float2(acc[mt][nt][rh * 2], acc[mt][nt][rh * 2 + 1]);
                    *(float2*)(outp + (size_t)row * NSP + col) = v2;
                }
            }
        __syncthreads();
    }
}

// ---------------------------------------------------------------------------
// Kernel 2: context partials. Conflict-free smem staging:
//   ks [32 d][132] float4 stores; vsT [128 j][36] built via 4-row LDG.64 gather
//   + STS.128 with egrp-fastest lane mapping (each 8-lane phase = 8 bank-groups)
// ---------------------------------------------------------------------------
__global__ void __launch_bounds__(256) k_reduce_kv() {
    __shared__ __align__(16) float ks[32 * 132];
    __shared__ __align__(16) float vsT[128 * 36];
    const int h = blockIdx.x, p = blockIdx.y, b = blockIdx.z;
    const int tid = threadIdx.x;
    const int d = tid >> 3;
    const int e4 = (tid & 7) << 2;
    const float* kb = g_qkv + ((size_t)b * 384 + 128 + h * DH) * NSP + p * 512;
    const float* vb = g_qkv + ((size_t)b * 384 + 256 + h * DH) * NSP + p * 512;

    u64 a01 = 0ull, a23 = 0ull;
    float zacc = 0.f;
    for (int ch = 0; ch < 4; ch++) {
        __syncthreads();
        // k tile: exp + float4 stores, stride 132 (conflict-free STS.128)
#pragma unroll
        for (int i = 0; i < 4; i++) {
            int idx4 = tid + i * 256;
            int r = idx4 >> 5, j4 = (idx4 & 31) << 2;
            float4 kv = *(const float4*)(kb + (size_t)r * NSP + ch * 128 + j4);
            float4 ev;
            if ((r & 15) < 7) {
                ev.x = exp_poly(kv.x); ev.y = exp_poly(kv.y);
                ev.z = exp_poly(kv.z); ev.w = exp_poly(kv.w);
            } else {
                ev.x = __expf(kv.x); ev.y = __expf(kv.y);
                ev.z = __expf(kv.z); ev.w = __expf(kv.w);
            }
            *(float4*)(ks + r * 132 + j4) = ev;
        }
        // v tile: gather 4 e-rows via LDG.64, transpose-store as STS.128
#pragma unroll
        for (int i = 0; i < 2; i++) {
            int task = tid + i * 256;
            int eg = task & 7;            // fastest across lanes -> distinct bank-groups
            int ve4 = eg << 2;
            int j2 = (task >> 3) & 63;
            const float* vp = vb + ch * 128 + j2 * 2;
            float2 v0 = *(const float2*)(vp + (size_t)(ve4 + 0) * NSP);
            float2 v1 = *(const float2*)(vp + (size_t)(ve4 + 1) * NSP);
            float2 v2 = *(const float2*)(vp + (size_t)(ve4 + 2) * NSP);
            float2 v3 = *(const float2*)(vp + (size_t)(ve4 + 3) * NSP);
            *(float4*)(vsT + (2 * j2) * 36 + ve4)     = make_float4(v0.x, v1.x, v2.x, v3.x);
            *(float4*)(vsT + (2 * j2 + 1) * 36 + ve4) = make_float4(v0.y, v1.y, v2.y, v3.y);
        }
        __syncthreads();
#pragma unroll 4
        for (int j = 0; j < 128; j++) {
            float kd = ks[d * 132 + j];
            u64 k2 = dup2(kd);
            ulonglong2 vv = *(const ulonglong2*)(vsT + j * 36 + e4);
            ffma2(a01, k2, vv.x);
            ffma2(a23, k2, vv.y);
            zacc += kd;
        }
    }
    float* Sp = g_Sp + (((size_t)(b * HEADS + h) * 8 + p) << 10);
    float2 f01 = unpk(a01), f23 = unpk(a23);
    Sp[d * 32 + e4 + 0] = f01.x;
    Sp[d * 32 + e4 + 1] = f01.y;
    Sp[d * 32 + e4 + 2] = f23.x;
    Sp[d * 32 + e4 + 3] = f23.y;
    if ((tid & 7) == 0) g_Zp[((b * HEADS + h) * 8 + p) * 32 + d] = zacc;
}

// ---------------------------------------------------------------------------
// Kernel 3: ctx = S/Z; M_b = Wout∘ctx, emitted as bf16 hi/lo split.
// grid = (32 batches, 8 o-slices) for parallelism (was the 52us laggard).
// ---------------------------------------------------------------------------
__global__ void __launch_bounds__(256) k_ctx_M(const float* __restrict__ Wout) {
    __shared__ float ctxs[4 * 32 * 33];
    __shared__ float zs[128];
    const int b = blockIdx.x;
    const int og = blockIdx.y;
    const int tid = threadIdx.x;
    if (tid < 128) {
        float z = 0.f;
#pragma unroll
        for (int p = 0; p < 8; p++)
            z += g_Zp[((b * HEADS + (tid >> 5)) * 8 + p) * 32 + (tid & 31)];
        zs[tid] = z;
    }
    __syncthreads();
    for (int idx = tid; idx < 4096; idx += 256) {
        int h = idx >> 10, d = (idx >> 5) & 31, e = idx & 31;
        float s = 0.f;
#pragma unroll
        for (int p = 0; p < 8; p++)
            s += g_Sp[(((size_t)(b * HEADS + h) * 8 + p) << 10) + d * 32 + e];
        ctxs[h * 1056 + d * 33 + e] = s / zs[h * 32 + d];
    }
    __syncthreads();
    unsigned short* Mh = g_Mbh + (size_t)b * 16384;
    unsigned short* Ml = g_Mbl + (size_t)b * 16384;
#pragma unroll
    for (int s8 = 0; s8 < 8; s8++) {
        int pidx = og * 2048 + tid + s8 * 256;
        int o = pidx >> 7, hd = pidx & 127;
        int h = hd >> 5, dd = hd & 31;
        const float* wrow = Wout + o * 128 + h * 32;
        const float* crow = ctxs + h * 1056 + dd * 33;
        float s = 0.f;
#pragma unroll
        for (int e = 0; e < 32; e++) s += __ldg(wrow + e) * crow[e];
        __nv_bfloat16 hb = __float2bfloat16(s);
        float hf = __bfloat162float(hb);
        Mh[pidx] = __bfloat16_as_ushort(hb);
        Ml[pidx] = __bfloat16_as_ushort(__float2bfloat16(s - hf));
    }
}

// ---------------------------------------------------------------------------
// Kernel 4 (tensorized): out = LayerNorm( M_b @ softmax_d(q) + bout )
// Softmax in fp32 stage -> bf16 hi/lo B tiles (k1 layout); A = pre-split M_b;
// split-bf16 mma; LN epilogue via shfl + smem reduction of fragment layout.
// ---------------------------------------------------------------------------
#define SMEM_K4 144384
__global__ void __launch_bounds__(256) k_out(const float* __restrict__ bout,
                                             const float* __restrict__ lnw,
                                             const float* __restrict__ lnb,
                                             float* __restrict__ out) {
    extern __shared__ char sm[];
    const u32 sbase = (u32)__cvta_generic_to_shared(sm);
    const u32 oBh = 0, oBl = 34816, oStage = 69632, oAh = 69632, oAl = 104448;
    float* stage = (float*)(sm + oStage);
    float* ssum  = (float*)(sm + 139264);   // 4*128 inv-sums
    float* red   = (float*)(sm + 141312);   // 4*128 partials
    float* meanv = (float*)(sm + 143360);   // 128
    float* rstd  = (float*)(sm + 143872);   // 128
    const int t = blockIdx.x, b = blockIdx.y;
    const int tid = threadIdx.x;
    const float* qb = g_qkv + (size_t)b * 384 * NSP + t * 128;

    // phase 1: q tile -> exp(q) in fp32 stage [k=128][132] (hybrid exp)
#pragma unroll
    for (int it = 0; it < 16; it++) {
        int u = tid + it * 256;
        int k = u >> 5, nc = (u & 31) << 2;
        float4 v = *(const float4*)(qb + (size_t)k * NSP + nc);
        float4 ev;
        if ((k & 15) < 6) {
            ev.x = exp_poly(v.x); ev.y = exp_poly(v.y);
            ev.z = exp_poly(v.z); ev.w = exp_poly(v.w);
        } else {
            ev.x = __expf(v.x); ev.y = __expf(v.y);
            ev.z = __expf(v.z); ev.w = __expf(v.w);
        }
        *(float4*)(stage + k * 132 + nc) = ev;
    }
    __syncthreads();

    // phase 2: per (head, col) inverse sums
#pragma unroll
    for (int s2 = 0; s2 < 2; s2++) {
        int idx = tid + s2 * 256;
        int n = idx & 127, hh = idx >> 7;
        float s = 0.f;
#pragma unroll
        for (int kk = 0; kk < 32; kk++) s += stage[(hh * 32 + kk) * 132 + n];
        ssum[hh * 128 + n] = 1.f / s;
    }
    __syncthreads();

    // phase 3: normalize + split to bf16 hi/lo in [n][k] layout
#pragma unroll
    for (int it = 0; it < 8; it++) {
        int v = tid + it * 256;
        int n = v & 127, k8 = v >> 7;
        float rn_ = ssum[(k8 >> 2) * 128 + n];
        float f[8];
#pragma unroll
        for (int j = 0; j < 8; j++) f[j] = stage[(k8 * 8 + j) * 132 + n] * rn_;
        u32 hw[4], lw[4];
#pragma unroll
        for (int jj = 0; jj < 4; jj++) {
            u32 hv;
            asm("cvt.rn.bf16x2.f32 %0,%1,%2;" : "=r"(hv) : "f"(f[2 * jj + 1]), "f"(f[2 * jj]));
            float hlo = __int_as_float((int)(hv << 16));
            float hhi = __int_as_float((int)(hv & 0xFFFF0000u));
            float rlo = f[2 * jj] - hlo, rhi = f[2 * jj + 1] - hhi;
            u32 lo;
            asm("cvt.rn.bf16x2.f32 %0,%1,%2;" : "=r"(lo) : "f"(rhi), "f"(rlo));
            hw[jj] = hv; lw[jj] = lo;
        }
        u32 off = n * 272 + k8 * 16;
        *(uint4*)(sm + oBh + off) = make_uint4(hw[0], hw[1], hw[2], hw[3]);
        *(uint4*)(sm + oBl + off) = make_uint4(lw[0], lw[1], lw[2], lw[3]);
    }
    __syncthreads();

    // phase 4: load A = pre-split M_b (overlays stage)
    {
        const uint4* gh = (const uint4*)(g_Mbh + (size_t)b * 16384);
        const uint4* gl = (const uint4*)(g_Mbl + (size_t)b * 16384);
#pragma unroll
        for (int it = 0; it < 8; it++) {
            int u = tid + it * 256;
            int r = u >> 4, c = u & 15;
            u32 off = r * 272 + c * 16;
            *(uint4*)(sm + oAh + off) = gh[r * 16 + c];
            *(uint4*)(sm + oAl + off) = gl[r * 16 + c];
        }
    }
    __syncthreads();

    const int l = tid & 31, wid = tid >> 5;
    const int wm = (wid & 3) * 32;
    const int nh = (wid >> 2) * 64;
    const u32 aoff = (u32)((wm + (l & 15)) * 272 + (l >> 4) * 16);
    const u32 boff = (u32)((nh + (l & 7) + ((l >> 4) << 3)) * 272 + (((l >> 3) & 1) << 4));

    float acc[2][8][4];
#pragma unroll
    for (int mt = 0; mt < 2; mt++)
#pragma unroll
        for (int nt = 0; nt < 8; nt++)
#pragma unroll
            for (int q = 0; q < 4; q++) acc[mt][nt][q] = 0.f;

#pragma unroll
    for (int kc = 0; kc < 8; kc++) {
        u32 ah[2][4], al_[2][4], bhf[4][4], blf[4][4];
#pragma unroll
        for (int mt = 0; mt < 2; mt++) {
            u32 o = aoff + mt * (16 * 272) + kc * 32;
            ldm4(ah[mt],  sbase + oAh + o);
            ldm4(al_[mt], sbase + oAl + o);
        }
#pragma unroll
        for (int p = 0; p < 4; p++) {
            u32 o = boff + p * (16 * 272) + kc * 32;
            ldm4(bhf[p], sbase + oBh + o);
            ldm4(blf[p], sbase + oBl + o);
        }
#pragma unroll
        for (int mt = 0; mt < 2; mt++)
#pragma unroll
            for (int nt = 0; nt < 8; nt++) {
                int p = nt >> 1, q = (nt & 1) * 2;
                mma16816(acc[mt][nt], ah[mt],  bhf[p][q], bhf[p][q + 1]);
                mma16816(acc[mt][nt], al_[mt], bhf[p][q], bhf[p][q + 1]);
                mma16816(acc[mt][nt], ah[mt],  blf[p][q], blf[p][q + 1]);
            }
    }

    // bias (row depends on mt, rh)
#pragma unroll
    for (int mt = 0; mt < 2; mt++)
#pragma unroll
        for (int rh = 0; rh < 2; rh++) {
            float bo = __ldg(bout + wm + mt * 16 + (l >> 2) + rh * 8);
#pragma unroll
            for (int nt = 0; nt < 8; nt++) {
                acc[mt][nt][rh * 2 + 0] += bo;
                acc[mt][nt][rh * 2 + 1] += bo;
            }
        }

    // LN pass 1: column means. Lane's 4 rows summed, shfl over lanes sharing col.
#pragma unroll
    for (int q = 0; q < 2; q++) {
#pragma unroll
        for (int nt = 0; nt < 8; nt++) {
            float cs = acc[0][nt][q] + acc[0][nt][2 + q] + acc[1][nt][q] + acc[1][nt][2 + q];
            cs += __shfl_xor_sync(0xffffffffu, cs, 4);
            cs += __shfl_xor_sync(0xffffffffu, cs, 8);
            cs += __shfl_xor_sync(0xffffffffu, cs, 16);
            if (l < 4) red[(wid & 3) * 128 + nh + nt * 8 + l * 2 + q] = cs;
        }
    }
    __syncthreads();
    if (tid < 128) {
        float s = red[tid] + red[128 + tid] + red[256 + tid] + red[384 + tid];
        meanv[tid] = s * (1.f / 128.f);
    }
    __syncthreads();
    // LN pass 2: column variances
#pragma unroll
    for (int q = 0; q < 2; q++) {
#pragma unroll
        for (int nt = 0; nt < 8; nt++) {
            float cm = meanv[nh + nt * 8 + (l & 3) * 2 + q];
            float d0 = acc[0][nt][q] - cm, d1 = acc[0][nt][2 + q] - cm;
            float d2 = acc[1][nt][q] - cm, d3 = acc[1][nt][2 + q] - cm;
            float cs = d0 * d0 + d1 * d1 + d2 * d2 + d3 * d3;
            cs += __shfl_xor_sync(0xffffffffu, cs, 4);
            cs += __shfl_xor_sync(0xffffffffu, cs, 8);
            cs += __shfl_xor_sync(0xffffffffu, cs, 16);
            if (l < 4) red[(wid & 3) * 128 + nh + nt * 8 + l * 2 + q] = cs;
        }
    }
    __syncthreads();
    if (tid < 128) {
        float s = red[tid] + red[128 + tid] + red[256 + tid] + red[384 + tid];
        rstd[tid] = rsqrtf(s * (1.f / 128.f) + EPS);
    }
    __syncthreads();

    // final: normalize, scale, store
#pragma unroll
    for (int mt = 0; mt < 2; mt++)
#pragma unroll
        for (int rh = 0; rh < 2; rh++) {
            int row = wm + mt * 16 + (l >> 2) + rh * 8;
            float lw = __ldg(lnw + row);
            float lb = __ldg(lnb + row);
#pragma unroll
            for (int nt = 0; nt < 8; nt++) {
                int col = nh + nt * 8 + (l & 3) * 2;
                float m0 = meanv[col], m1 = meanv[col + 1];
                float r0 = rstd[col], r1 = rstd[col + 1];
                float2 o2;
                o2.x = (acc[mt][nt][rh * 2 + 0] - m0) * r0 * lw + lb;
                o2.y = (acc[mt][nt][rh * 2 + 1] - m1) * r1 * lw + lb;
                *(float2*)(out + ((size_t)b * CDIM + row) * NSP + t * 128 + col) = o2;
            }
        }
}

// ---------------------------------------------------------------------------
extern "C" void kernel_launch(void* const* d_in, const int* in_sizes, int n_in,
                              void* d_out, int out_size) {
    const float* x    = (const float*)d_in[0];
    const float* Wqkv = (const float*)d_in[1];
    const float* Wout = (const float*)d_in[2];
    const float* bout = (const float*)d_in[3];
    const float* lnw  = (const float*)d_in[4];
    const float* lnb  = (const float*)d_in[5];
    float* out = (float*)d_out;

    cudaFuncSetAttribute(k_gemm_qkv, cudaFuncAttributeMaxDynamicSharedMemorySize, SMEM_K1);
    cudaFuncSetAttribute(k_out, cudaFuncAttributeMaxDynamicSharedMemorySize, SMEM_K4);

    k_splitW<<<48, 256>>>(Wqkv);
    k_gemm_qkv<<<dim3(32, B), 256, SMEM_K1>>>(x);
    k_reduce_kv<<<dim3(HEADS, 8, B), 256>>>();
    k_ctx_M<<<dim3(B, 8), 256>>>(Wout);
    k_out<<<dim3(32, B), 256, SMEM_K4>>>(bout, lnw, lnb, out);
}

// round 7
// speedup vs baseline: 2.1670x; 1.1452x over previous
#include <cuda_runtime.h>
#include <cuda_bf16.h>
#include <math.h>

#define B    32
#define CDIM 128
#define NSP  4096
#define HEADS 4
#define DH   32
#define EPS  1e-5f

typedef unsigned long long u64;
typedef unsigned int u32;

// ---------------- FFMA-only exp ----------------
__device__ __forceinline__ float exp_poly(float x) {
    float y = x * 1.4426950408889634f;
    float z = y + 12582912.0f;
    int   zb = __float_as_int(z);
    float n = z - 12582912.0f;
    float f = y - n;
    float p = 0.0096180f;
    p = fmaf(p, f, 0.0555041f);
    p = fmaf(p, f, 0.2402265f);
    p = fmaf(p, f, 0.6931472f);
    p = fmaf(p, f, 1.0f);
    return __int_as_float(__float_as_int(p) + (zb << 23));
}

// ---------------- mma.sync / ldmatrix wrappers ----------------
__device__ __forceinline__ void ldm4(u32* d, u32 addr) {
    asm volatile("ldmatrix.sync.aligned.m8n8.x4.shared.b16 {%0,%1,%2,%3},[%4];"
                 : "=r"(d[0]), "=r"(d[1]), "=r"(d[2]), "=r"(d[3]) : "r"(addr));
}
__device__ __forceinline__ void mma16816(float* c, const u32* a, u32 b0, u32 b1) {
    asm volatile("mma.sync.aligned.m16n8k16.row.col.f32.bf16.bf16.f32 "
                 "{%0,%1,%2,%3},{%4,%5,%6,%7},{%8,%9},{%0,%1,%2,%3};"
                 : "+f"(c[0]), "+f"(c[1]), "+f"(c[2]), "+f"(c[3])
                 : "r"(a[0]), "r"(a[1]), "r"(a[2]), "r"(a[3]), "r"(b0), "r"(b1));
}

// split a float4 into bf16x2 hi/lo packed words
__device__ __forceinline__ void split4(float4 v, u32& h0, u32& h1, u32& l0, u32& l1) {
    asm("cvt.rn.bf16x2.f32 %0,%1,%2;" : "=r"(h0) : "f"(v.y), "f"(v.x));
    asm("cvt.rn.bf16x2.f32 %0,%1,%2;" : "=r"(h1) : "f"(v.w), "f"(v.z));
    float r0 = v.x - __int_as_float((int)(h0 << 16));
    float r1 = v.y - __int_as_float((int)(h0 & 0xFFFF0000u));
    float r2 = v.z - __int_as_float((int)(h1 << 16));
    float r3 = v.w - __int_as_float((int)(h1 & 0xFFFF0000u));
    asm("cvt.rn.bf16x2.f32 %0,%1,%2;" : "=r"(l0) : "f"(r1), "f"(r0));
    asm("cvt.rn.bf16x2.f32 %0,%1,%2;" : "=r"(l1) : "f"(r3), "f"(r2));
}

// ---------------- scratch ----------------
__device__ float g_qkv[(size_t)B * 384 * NSP];
__device__ float g_Sp[(size_t)B * HEADS * 8 * DH * DH];
__device__ float g_Zp[(size_t)B * HEADS * 8 * DH];
__device__ float g_ctx[(size_t)B * 4096];
__device__ __align__(16) unsigned short g_Wh[384 * 128];
__device__ __align__(16) unsigned short g_Wl[384 * 128];
__device__ __align__(16) unsigned short g_Mbh[(size_t)B * 16384];
__device__ __align__(16) unsigned short g_Mbl[(size_t)B * 16384];

// ---------------------------------------------------------------------------
// Kernel 0: split Wqkv into bf16 hi/lo
// ---------------------------------------------------------------------------
__global__ void k_splitW(const float* __restrict__ W) {
    for (int i = blockIdx.x * blockDim.x + threadIdx.x; i < 384 * 128;
         i += gridDim.x * blockDim.x) {
        float w = W[i];
        __nv_bfloat16 hb = __float2bfloat16(w);
        float hf = __bfloat162float(hb);
        __nv_bfloat16 lb = __float2bfloat16(w - hf);
        g_Wh[i] = __bfloat16_as_ushort(hb);
        g_Wl[i] = __bfloat16_as_ushort(lb);
    }
}

// ---------------------------------------------------------------------------
// Kernel 1: qkv = Wqkv @ x via split-bf16 mma.sync (unchanged, proven)
// ---------------------------------------------------------------------------
#define SMEM_K1 139264
__global__ void __launch_bounds__(256) k_gemm_qkv(const float* __restrict__ x) {
    extern __shared__ char sm[];
    const u32 sbase = (u32)__cvta_generic_to_shared(sm);
    const u32 oBh = 0, oBl = 34816, oStage = 69632, oAh = 69632, oAl = 104448;
    float* stage = (float*)(sm + oStage);
    const int t = blockIdx.x, b = blockIdx.y;
    const int tid = threadIdx.x;
    const float* xb = x + (size_t)b * CDIM * NSP + t * 128;

#pragma unroll
    for (int it = 0; it < 16; it++) {
        int u = tid + it * 256;
        int k = u >> 5, nc = (u & 31) << 2;
        float4 v = *(const float4*)(xb + (size_t)k * NSP + nc);
        *(float4*)(stage + k * 132 + nc) = v;
    }
    __syncthreads();

#pragma unroll
    for (int it = 0; it < 8; it++) {
        int v = tid + it * 256;
        int n = v & 127, k8 = v >> 7;
        float f[8];
#pragma unroll
        for (int j = 0; j < 8; j++) f[j] = stage[(k8 * 8 + j) * 132 + n];
        u32 hw[4], lw[4];
#pragma unroll
        for (int jj = 0; jj < 2; jj++) {
            float4 q4 = make_float4(f[4 * jj], f[4 * jj + 1], f[4 * jj + 2], f[4 * jj + 3]);
            split4(q4, hw[2 * jj], hw[2 * jj + 1], lw[2 * jj], lw[2 * jj + 1]);
        }
        u32 off = n * 272 + k8 * 16;
        *(uint4*)(sm + oBh + off) = make_uint4(hw[0], hw[1], hw[2], hw[3]);
        *(uint4*)(sm + oBl + off) = make_uint4(lw[0], lw[1], lw[2], lw[3]);
    }
    __syncthreads();

    const int l = tid & 31, wid = tid >> 5;
    const int wm = (wid & 3) * 32;
    const int nh = (wid >> 2) * 64;
    const u32 aoff = (u32)((wm + (l & 15)) * 272 + (l >> 4) * 16);
    const u32 boff = (u32)((nh + (l & 7) + ((l >> 4) << 3)) * 272 + (((l >> 3) & 1) << 4));

    for (int rb = 0; rb < 3; rb++) {
        {
            const uint4* gh = (const uint4*)(g_Wh + (size_t)rb * 128 * 128);
            const uint4* gl = (const uint4*)(g_Wl + (size_t)rb * 128 * 128);
#pragma unroll
            for (int it = 0; it < 8; it++) {
                int u = tid + it * 256;
                int r = u >> 4, c = u & 15;
                u32 off = r * 272 + c * 16;
                *(uint4*)(sm + oAh + off) = gh[r * 16 + c];
                *(uint4*)(sm + oAl + off) = gl[r * 16 + c];
            }
        }
        __syncthreads();

        float acc[2][8][4];
#pragma unroll
        for (int mt = 0; mt < 2; mt++)
#pragma unroll
            for (int nt = 0; nt < 8; nt++)
#pragma unroll
                for (int q = 0; q < 4; q++) acc[mt][nt][q] = 0.f;

#pragma unroll
        for (int kc = 0; kc < 8; kc++) {
            u32 ah[2][4], al_[2][4], bhf[4][4], blf[4][4];
#pragma unroll
            for (int mt = 0; mt < 2; mt++) {
                u32 o = aoff + mt * (16 * 272) + kc * 32;
                ldm4(ah[mt],  sbase + oAh + o);
                ldm4(al_[mt], sbase + oAl + o);
            }
#pragma unroll
            for (int p = 0; p < 4; p++) {
                u32 o = boff + p * (16 * 272) + kc * 32;
                ldm4(bhf[p], sbase + oBh + o);
                ldm4(blf[p], sbase + oBl + o);
            }
#pragma unroll
            for (int mt = 0; mt < 2; mt++)
#pragma unroll
                for (int nt = 0; nt < 8; nt++) {
                    int p = nt >> 1, q = (nt & 1) * 2;
                    mma16816(acc[mt][nt], ah[mt],  bhf[p][q], bhf[p][q + 1]);
                    mma16816(acc[mt][nt], al_[mt], bhf[p][q], bhf[p][q + 1]);
                    mma16816(acc[mt][nt], ah[mt],  blf[p][q], blf[p][q + 1]);
                }
        }

        float* outp = g_qkv + ((size_t)b * 384 + rb * 128) * NSP + t * 128;
#pragma unroll
        for (int mt = 0; mt < 2; mt++)
#pragma unroll
            for (int rh = 0; rh < 2; rh++) {
                int row = wm + mt * 16 + (l >> 2) + rh * 8;
#pragma unroll
                for (int nt = 0; nt < 8; nt++) {
                    int col = nh + nt * 8 + (l & 3) * 2;
                    float2 v2 = make_float2(acc[mt][nt][rh * 2], acc[mt][nt][rh * 2 + 1]);
                    *(float2*)(outp + (size_t)row * NSP + col) = v2;
                }
            }
        __syncthreads();
    }
}

// ---------------------------------------------------------------------------
// Kernel 2 (TENSORIZED): Sp[d][e] = sum_n exp(k[d,n])*v[e,n] via split-bf16 mma
// Z via exact fp32 warp reduction during the exp pass (warp owns whole rows).
// Warp w: mt=w&1 (m16), np=(w>>1)&1 (n16), kh=w>>2 (k-half); smem kh-reduce.
// grid = (4 heads, 8 slabs of 512 n, 32 batches)
// ---------------------------------------------------------------------------
__global__ void __launch_bounds__(256) k_reduce_kv() {
    __shared__ __align__(16) char sm2[34816 + 4224];
    const u32 sbase = (u32)__cvta_generic_to_shared(sm2);
    const u32 oAh = 0, oAl = 8704, oBh = 17408, oBl = 26112;
    float* sbuf = (float*)(sm2 + 34816);
    const int h = blockIdx.x, p = blockIdx.y, b = blockIdx.z;
    const int tid = threadIdx.x;
    const int l = tid & 31, w = tid >> 5;
    const float* kb = g_qkv + ((size_t)b * 384 + 128 + h * DH) * NSP + p * 512;
    const float* vb = g_qkv + ((size_t)b * 384 + 256 + h * DH) * NSP + p * 512;

    const int mt = w & 1, np = (w >> 1) & 1, kh = w >> 2;
    const u32 aoff = (u32)((mt * 16 + (l & 15)) * 272 + (l >> 4) * 16);
    const u32 boff = (u32)((np * 16 + (l & 7) + ((l >> 4) << 3)) * 272 + (((l >> 3) & 1) << 4));

    float acc[2][4];
#pragma unroll
    for (int g = 0; g < 2; g++)
#pragma unroll
        for (int q = 0; q < 4; q++) acc[g][q] = 0.f;
    float zreg[4] = {0.f, 0.f, 0.f, 0.f};

    for (int ch = 0; ch < 4; ch++) {
        __syncthreads();
        // K rows: exp (hybrid) + split; warp w owns rows d = w + 8i
#pragma unroll
        for (int i = 0; i < 4; i++) {
            int d = w + i * 8;
            float4 kv = *(const float4*)(kb + (size_t)d * NSP + ch * 128 + l * 4);
            float4 ev;
            if ((d & 15) < 12) {
                ev.x = exp_poly(kv.x); ev.y = exp_poly(kv.y);
                ev.z = exp_poly(kv.z); ev.w = exp_poly(kv.w);
            } else {
                ev.x = __expf(kv.x); ev.y = __expf(kv.y);
                ev.z = __expf(kv.z); ev.w = __expf(kv.w);
            }
            float s4 = ev.x + ev.y + ev.z + ev.w;
            s4 += __shfl_xor_sync(0xffffffffu, s4, 1);
            s4 += __shfl_xor_sync(0xffffffffu, s4, 2);
            s4 += __shfl_xor_sync(0xffffffffu, s4, 4);
            s4 += __shfl_xor_sync(0xffffffffu, s4, 8);
            s4 += __shfl_xor_sync(0xffffffffu, s4, 16);
            zreg[i] += s4;
            u32 h0, h1, l0, l1;
            split4(ev, h0, h1, l0, l1);
            *(uint2*)(sm2 + oAh + d * 272 + l * 8) = make_uint2(h0, h1);
            *(uint2*)(sm2 + oAl + d * 272 + l * 8) = make_uint2(l0, l1);
        }
        // V rows: split
#pragma unroll
        for (int i = 0; i < 4; i++) {
            int e = w + i * 8;
            float4 vv = *(const float4*)(vb + (size_t)e * NSP + ch * 128 + l * 4);
            u32 h0, h1, l0, l1;
            split4(vv, h0, h1, l0, l1);
            *(uint2*)(sm2 + oBh + e * 272 + l * 8) = make_uint2(h0, h1);
            *(uint2*)(sm2 + oBl + e * 272 + l * 8) = make_uint2(l0, l1);
        }
        __syncthreads();
        // mma over this warp's k-half
#pragma unroll
        for (int kc2 = 0; kc2 < 4; kc2++) {
            int kc = kh * 4 + kc2;
            u32 ah[4], al_[4], bh_[4], bl_[4];
            ldm4(ah,  sbase + oAh + aoff + kc * 32);
            ldm4(al_, sbase + oAl + aoff + kc * 32);
            ldm4(bh_, sbase + oBh + boff + kc * 32);
            ldm4(bl_, sbase + oBl + boff + kc * 32);
#pragma unroll
            for (int g = 0; g < 2; g++) {
                mma16816(acc[g], ah,  bh_[g * 2], bh_[g * 2 + 1]);
                mma16816(acc[g], al_, bh_[g * 2], bh_[g * 2 + 1]);
                mma16816(acc[g], ah,  bl_[g * 2], bl_[g * 2 + 1]);
            }
        }
    }

    // kh reduction through sbuf [32][33]
    __syncthreads();
    if (kh == 0) {
#pragma unroll
        for (int g = 0; g < 2; g++)
#pragma unroll
            for (int rh = 0; rh < 2; rh++)
#pragma unroll
                for (int q = 0; q < 2; q++) {
                    int row = mt * 16 + (l >> 2) + rh * 8;
                    int col = np * 16 + g * 8 + (l & 3) * 2 + q;
                    sbuf[row * 33 + col] = acc[g][rh * 2 + q];
                }
    }
    __syncthreads();
    if (kh == 1) {
#pragma unroll
        for (int g = 0; g < 2; g++)
#pragma unroll
            for (int rh = 0; rh < 2; rh++)
#pragma unroll
                for (int q = 0; q < 2; q++) {
                    int row = mt * 16 + (l >> 2) + rh * 8;
                    int col = np * 16 + g * 8 + (l & 3) * 2 + q;
                    sbuf[row * 33 + col] += acc[g][rh * 2 + q];
                }
    }
    __syncthreads();
    float* Sp = g_Sp + (((size_t)(b * HEADS + h) * 8 + p) << 10);
#pragma unroll
    for (int i2 = 0; i2 < 4; i2++) {
        int idx = tid + i2 * 256;
        Sp[idx] = sbuf[(idx >> 5) * 33 + (idx & 31)];
    }
    if (l == 0) {
#pragma unroll
        for (int i = 0; i < 4; i++)
            g_Zp[((b * HEADS + h) * 8 + p) * 32 + w + i * 8] = zreg[i];
    }
}

// ---------------------------------------------------------------------------
// Kernel 3a: ctx = (sum_p Sp) / Z  -> g_ctx   (grid 32)
// ---------------------------------------------------------------------------
__global__ void __launch_bounds__(256) k_ctx(const float* __restrict__ dummy) {
    __shared__ float zs[128];
    const int b = blockIdx.x;
    const int tid = threadIdx.x;
    if (tid < 128) {
        float z = 0.f;
#pragma unroll
        for (int p = 0; p < 8; p++)
            z += g_Zp[((b * HEADS + (tid >> 5)) * 8 + p) * 32 + (tid & 31)];
        zs[tid] = z;
    }
    __syncthreads();
#pragma unroll
    for (int s2 = 0; s2 < 16; s2++) {
        int idx = tid + s2 * 256;
        int h = idx >> 10, d = (idx >> 5) & 31;
        float s = 0.f;
#pragma unroll
        for (int p = 0; p < 8; p++)
            s += g_Sp[(((size_t)(b * HEADS + h) * 8 + p) << 10) + (idx & 1023)];
        g_ctx[(size_t)b * 4096 + idx] = s / zs[h * 32 + d];
    }
}

// ---------------------------------------------------------------------------
// Kernel 3b: M_b[o][hd] = sum_e Wout[o][h*32+e]*ctx[h][d][e], bf16 hi/lo out
// grid = (32 batches, 8 o-slices)
// ---------------------------------------------------------------------------
__global__ void __launch_bounds__(256) k_M(const float* __restrict__ Wout) {
    __shared__ float ctxs[4 * 32 * 33];
    const int b = blockIdx.x;
    const int og = blockIdx.y;
    const int tid = threadIdx.x;
#pragma unroll
    for (int s2 = 0; s2 < 16; s2++) {
        int idx = tid + s2 * 256;
        int h = idx >> 10, d = (idx >> 5) & 31, e = idx & 31;
        ctxs[h * 1056 + d * 33 + e] = g_ctx[(size_t)b * 4096 + idx];
    }
    __syncthreads();
    unsigned short* Mh = g_Mbh + (size_t)b * 16384;
    unsigned short* Ml = g_Mbl + (size_t)b * 16384;
#pragma unroll
    for (int s8 = 0; s8 < 8; s8++) {
        int pidx = og * 2048 + tid + s8 * 256;
        int o = pidx >> 7, hd = pidx & 127;
        int h = hd >> 5, dd = hd & 31;
        const float* wrow = Wout + o * 128 + h * 32;
        const float* crow = ctxs + h * 1056 + dd * 33;
        float s = 0.f;
#pragma unroll
        for (int e = 0; e < 32; e++) s += __ldg(wrow + e) * crow[e];
        __nv_bfloat16 hb = __float2bfloat16(s);
        float hf = __bfloat162float(hb);
        Mh[pidx] = __bfloat16_as_ushort(hb);
        Ml[pidx] = __bfloat16_as_ushort(__float2bfloat16(s - hf));
    }
}

// ---------------------------------------------------------------------------
// Kernel 4: out = LayerNorm( M_b @ softmax_d(q) + bout ), tensorized,
// exp hybrid p=12/16 poly.
// ---------------------------------------------------------------------------
#define SMEM_K4 144384
__global__ void __launch_bounds__(256) k_out(const float* __restrict__ bout,
                                             const float* __restrict__ lnw,
                                             const float* __restrict__ lnb,
                                             float* __restrict__ out) {
    extern __shared__ char sm[];
    const u32 sbase = (u32)__cvta_generic_to_shared(sm);
    const u32 oBh = 0, oBl = 34816, oStage = 69632, oAh = 69632, oAl = 104448;
    float* stage = (float*)(sm + oStage);
    float* ssum  = (float*)(sm + 139264);
    float* red   = (float*)(sm + 141312);
    float* meanv = (float*)(sm + 143360);
    float* rstd  = (float*)(sm + 143872);
    const int t = blockIdx.x, b = blockIdx.y;
    const int tid = threadIdx.x;
    const float* qb = g_qkv + (size_t)b * 384 * NSP + t * 128;

#pragma unroll
    for (int it = 0; it < 16; it++) {
        int u = tid + it * 256;
        int k = u >> 5, nc = (u & 31) << 2;
        float4 v = *(const float4*)(qb + (size_t)k * NSP + nc);
        float4 ev;
        if ((k & 15) < 12) {
            ev.x = exp_poly(v.x); ev.y = exp_poly(v.y);
            ev.z = exp_poly(v.z); ev.w = exp_poly(v.w);
        } else {
            ev.x = __expf(v.x); ev.y = __expf(v.y);
            ev.z = __expf(v.z); ev.w = __expf(v.w);
        }
        *(float4*)(stage + k * 132 + nc) = ev;
    }
    __syncthreads();

#pragma unroll
    for (int s2 = 0; s2 < 2; s2++) {
        int idx = tid + s2 * 256;
        int n = idx & 127, hh = idx >> 7;
        float s = 0.f;
#pragma unroll
        for (int kk = 0; kk < 32; kk++) s += stage[(hh * 32 + kk) * 132 + n];
        ssum[hh * 128 + n] = 1.f / s;
    }
    __syncthreads();

#pragma unroll
    for (int it = 0; it < 8; it++) {
        int v = tid + it * 256;
        int n = v & 127, k8 = v >> 7;
        float rn_ = ssum[(k8 >> 2) * 128 + n];
        u32 hw[4], lw[4];
#pragma unroll
        for (int jj = 0; jj < 2; jj++) {
            float4 q4;
            q4.x = stage[(k8 * 8 + 4 * jj + 0) * 132 + n] * rn_;
            q4.y = stage[(k8 * 8 + 4 * jj + 1) * 132 + n] * rn_;
            q4.z = stage[(k8 * 8 + 4 * jj + 2) * 132 + n] * rn_;
            q4.w = stage[(k8 * 8 + 4 * jj + 3) * 132 + n] * rn_;
            split4(q4, hw[2 * jj], hw[2 * jj + 1], lw[2 * jj], lw[2 * jj + 1]);
        }
        u32 off = n * 272 + k8 * 16;
        *(uint4*)(sm + oBh + off) = make_uint4(hw[0], hw[1], hw[2], hw[3]);
        *(uint4*)(sm + oBl + off) = make_uint4(lw[0], lw[1], lw[2], lw[3]);
    }
    __syncthreads();

    {
        const uint4* gh = (const uint4*)(g_Mbh + (size_t)b * 16384);
        const uint4* gl = (const uint4*)(g_Mbl + (size_t)b * 16384);
#pragma unroll
        for (int it = 0; it < 8; it++) {
            int u = tid + it * 256;
            int r = u >> 4, c = u & 15;
            u32 off = r * 272 + c * 16;
            *(uint4*)(sm + oAh + off) = gh[r * 16 + c];
            *(uint4*)(sm + oAl + off) = gl[r * 16 + c];
        }
    }
    __syncthreads();

    const int l = tid & 31, wid = tid >> 5;
    const int wm = (wid & 3) * 32;
    const int nh = (wid >> 2) * 64;
    const u32 aoff = (u32)((wm + (l & 15)) * 272 + (l >> 4) * 16);
    const u32 boff = (u32)((nh + (l & 7) + ((l >> 4) << 3)) * 272 + (((l >> 3) & 1) << 4));

    float acc[2][8][4];
#pragma unroll
    for (int mt = 0; mt < 2; mt++)
#pragma unroll
        for (int nt = 0; nt < 8; nt++)
#pragma unroll
            for (int q = 0; q < 4; q++) acc[mt][nt][q] = 0.f;

#pragma unroll
    for (int kc = 0; kc < 8; kc++) {
        u32 ah[2][4], al_[2][4], bhf[4][4], blf[4][4];
#pragma unroll
        for (int mt = 0; mt < 2; mt++) {
            u32 o = aoff + mt * (16 * 272) + kc * 32;
            ldm4(ah[mt],  sbase + oAh + o);
            ldm4(al_[mt], sbase + oAl + o);
        }
#pragma unroll
        for (int p = 0; p < 4; p++) {
            u32 o = boff + p * (16 * 272) + kc * 32;
            ldm4(bhf[p], sbase + oBh + o);
            ldm4(blf[p], sbase + oBl + o);
        }
#pragma unroll
        for (int mt = 0; mt < 2; mt++)
#pragma unroll
            for (int nt = 0; nt < 8; nt++) {
                int p = nt >> 1, q = (nt & 1) * 2;
                mma16816(acc[mt][nt], ah[mt],  bhf[p][q], bhf[p][q + 1]);
                mma16816(acc[mt][nt], al_[mt], bhf[p][q], bhf[p][q + 1]);
                mma16816(acc[mt][nt], ah[mt],  blf[p][q], blf[p][q + 1]);
            }
    }

#pragma unroll
    for (int mt = 0; mt < 2; mt++)
#pragma unroll
        for (int rh = 0; rh < 2; rh++) {
            float bo = __ldg(bout + wm + mt * 16 + (l >> 2) + rh * 8);
#pragma unroll
            for (int nt = 0; nt < 8; nt++) {
                acc[mt][nt][rh * 2 + 0] += bo;
                acc[mt][nt][rh * 2 + 1] += bo;
            }
        }

#pragma unroll
    for (int q = 0; q < 2; q++) {
#pragma unroll
        for (int nt = 0; nt < 8; nt++) {
            float cs = acc[0][nt][q] + acc[0][nt][2 + q] + acc[1][nt][q] + acc[1][nt][2 + q];
            cs += __shfl_xor_sync(0xffffffffu, cs, 4);
            cs += __shfl_xor_sync(0xffffffffu, cs, 8);
            cs += __shfl_xor_sync(0xffffffffu, cs, 16);
            if (l < 4) red[(wid & 3) * 128 + nh + nt * 8 + l * 2 + q] = cs;
        }
    }
    __syncthreads();
    if (tid < 128) {
        float s = red[tid] + red[128 + tid] + red[256 + tid] + red[384 + tid];
        meanv[tid] = s * (1.f / 128.f);
    }
    __syncthreads();
#pragma unroll
    for (int q = 0; q < 2; q++) {
#pragma unroll
        for (int nt = 0; nt < 8; nt++) {
            float cm = meanv[nh + nt * 8 + (l & 3) * 2 + q];
            float d0 = acc[0][nt][q] - cm, d1 = acc[0][nt][2 + q] - cm;
            float d2 = acc[1][nt][q] - cm, d3 = acc[1][nt][2 + q] - cm;
            float cs = d0 * d0 + d1 * d1 + d2 * d2 + d3 * d3;
            cs += __shfl_xor_sync(0xffffffffu, cs, 4);
            cs += __shfl_xor_sync(0xffffffffu, cs, 8);
            cs += __shfl_xor_sync(0xffffffffu, cs, 16);
            if (l < 4) red[(wid & 3) * 128 + nh + nt * 8 + l * 2 + q] = cs;
        }
    }
    __syncthreads();
    if (tid < 128) {
        float s = red[tid] + red[128 + tid] + red[256 + tid] + red[384 + tid];
        rstd[tid] = rsqrtf(s * (1.f / 128.f) + EPS);
    }
    __syncthreads();

#pragma unroll
    for (int mt = 0; mt < 2; mt++)
#pragma unroll
        for (int rh = 0; rh < 2; rh++) {
            int row = wm + mt * 16 + (l >> 2) + rh * 8;
            float lw = __ldg(lnw + row);
            float lb = __ldg(lnb + row);
#pragma unroll
            for (int nt = 0; nt < 8; nt++) {
                int col = nh + nt * 8 + (l & 3) * 2;
                float m0 = meanv[col], m1 = meanv[col + 1];
                float r0 = rstd[col], r1 = rstd[col + 1];
                float2 o2;
                o2.x = (acc[mt][nt][rh * 2 + 0] - m0) * r0 * lw + lb;
                o2.y = (acc[mt][nt][rh * 2 + 1] - m1) * r1 * lw + lb;
                *(float2*)(out + ((size_t)b * CDIM + row) * NSP + t * 128 + col) = o2;
            }
        }
}

// ---------------------------------------------------------------------------
extern "C" void kernel_launch(void* const* d_in, const int* in_sizes, int n_in,
                              void* d_out, int out_size) {
    const float* x    = (const float*)d_in[0];
    const float* Wqkv = (const float*)d_in[1];
    const float* Wout = (const float*)d_in[2];
    const float* bout = (const float*)d_in[3];
    const float* lnw  = (const float*)d_in[4];
    const float* lnb  = (const float*)d_in[5];
    float* out = (float*)d_out;

    cudaFuncSetAttribute(k_gemm_qkv, cudaFuncAttributeMaxDynamicSharedMemorySize, SMEM_K1);
    cudaFuncSetAttribute(k_out, cudaFuncAttributeMaxDynamicSharedMemorySize, SMEM_K4);

    k_splitW<<<48, 256>>>(Wqkv);
    k_gemm_qkv<<<dim3(32, B), 256, SMEM_K1>>>(x);
    k_reduce_kv<<<dim3(HEADS, 8, B), 256>>>();
    k_ctx<<<B, 256>>>(nullptr);
    k_M<<<dim3(B, 8), 256>>>(Wout);
    k_out<<<dim3(32, B), 256, SMEM_K4>>>(bout, lnw, lnb, out);
}

// round 8
// speedup vs baseline: 2.2144x; 1.0219x over previous
#include <cuda_runtime.h>
#include <cuda_bf16.h>
#include <math.h>

#define B    32
#define CDIM 128
#define NSP  4096
#define HEADS 4
#define DH   32
#define EPS  1e-5f

typedef unsigned long long u64;
typedef unsigned int u32;

// ---------------- FFMA-only exp ----------------
__device__ __forceinline__ float exp_poly(float x) {
    float y = x * 1.4426950408889634f;
    float z = y + 12582912.0f;
    int   zb = __float_as_int(z);
    float n = z - 12582912.0f;
    float f = y - n;
    float p = 0.0096180f;
    p = fmaf(p, f, 0.0555041f);
    p = fmaf(p, f, 0.2402265f);
    p = fmaf(p, f, 0.6931472f);
    p = fmaf(p, f, 1.0f);
    return __int_as_float(__float_as_int(p) + (zb << 23));
}

// ---------------- mma.sync / ldmatrix wrappers ----------------
__device__ __forceinline__ void ldm4(u32* d, u32 addr) {
    asm volatile("ldmatrix.sync.aligned.m8n8.x4.shared.b16 {%0,%1,%2,%3},[%4];"
                 : "=r"(d[0]), "=r"(d[1]), "=r"(d[2]), "=r"(d[3]) : "r"(addr));
}
__device__ __forceinline__ void mma16816(float* c, const u32* a, u32 b0, u32 b1) {
    asm volatile("mma.sync.aligned.m16n8k16.row.col.f32.bf16.bf16.f32 "
                 "{%0,%1,%2,%3},{%4,%5,%6,%7},{%8,%9},{%0,%1,%2,%3};"
                 : "+f"(c[0]), "+f"(c[1]), "+f"(c[2]), "+f"(c[3])
                 : "r"(a[0]), "r"(a[1]), "r"(a[2]), "r"(a[3]), "r"(b0), "r"(b1));
}

// split a float4 into bf16x2 hi/lo packed words
__device__ __forceinline__ void split4(float4 v, u32& h0, u32& h1, u32& l0, u32& l1) {
    asm("cvt.rn.bf16x2.f32 %0,%1,%2;" : "=r"(h0) : "f"(v.y), "f"(v.x));
    asm("cvt.rn.bf16x2.f32 %0,%1,%2;" : "=r"(h1) : "f"(v.w), "f"(v.z));
    float r0 = v.x - __int_as_float((int)(h0 << 16));
    float r1 = v.y - __int_as_float((int)(h0 & 0xFFFF0000u));
    float r2 = v.z - __int_as_float((int)(h1 << 16));
    float r3 = v.w - __int_as_float((int)(h1 & 0xFFFF0000u));
    asm("cvt.rn.bf16x2.f32 %0,%1,%2;" : "=r"(l0) : "f"(r1), "f"(r0));
    asm("cvt.rn.bf16x2.f32 %0,%1,%2;" : "=r"(l1) : "f"(r3), "f"(r2));
}

// ---------------- scratch ----------------
__device__ float g_qkv[(size_t)B * 384 * NSP];
__device__ float g_Sp[(size_t)B * HEADS * 4 * DH * DH];
__device__ float g_Zp[(size_t)B * HEADS * 4 * DH];
__device__ __align__(16) unsigned short g_Wh[384 * 128];
__device__ __align__(16) unsigned short g_Wl[384 * 128];
__device__ __align__(16) unsigned short g_Mbh[(size_t)B * 16384];
__device__ __align__(16) unsigned short g_Mbl[(size_t)B * 16384];

// ---------------------------------------------------------------------------
// Kernel 0: split Wqkv into bf16 hi/lo
// ---------------------------------------------------------------------------
__global__ void k_splitW(const float* __restrict__ W) {
    for (int i = blockIdx.x * blockDim.x + threadIdx.x; i < 384 * 128;
         i += gridDim.x * blockDim.x) {
        float w = W[i];
        __nv_bfloat16 hb = __float2bfloat16(w);
        float hf = __bfloat162float(hb);
        __nv_bfloat16 lb = __float2bfloat16(w - hf);
        g_Wh[i] = __bfloat16_as_ushort(hb);
        g_Wl[i] = __bfloat16_as_ushort(lb);
    }
}

// ---------------------------------------------------------------------------
// Kernel 1: qkv = Wqkv @ x, split-bf16 mma, 64-wide n tiles, 2 CTAs/SM.
// smem: Bh[64n][272B], Bl; overlay { stage[128k][68f] } with { Ah, Al }.
// grid = (64 n-tiles, 32 batches), 256 threads (8 warps: 4 m x 2 n).
// ---------------------------------------------------------------------------
#define SMEM_K1 104448
__global__ void __launch_bounds__(256) k_gemm_qkv(const float* __restrict__ x) {
    extern __shared__ char sm[];
    const u32 sbase = (u32)__cvta_generic_to_shared(sm);
    const u32 oBh = 0, oBl = 17408, oAh = 34816, oAl = 69632;
    float* stage = (float*)(sm + oAh);       // overlays Ah region (34816 B)
    const int t = blockIdx.x, b = blockIdx.y;
    const int tid = threadIdx.x;
    const float* xb = x + (size_t)b * CDIM * NSP + t * 64;

    // phase 1: x tile [128k][64n] -> fp32 stage stride 68
#pragma unroll
    for (int it = 0; it < 8; it++) {
        int u = tid + it * 256;
        int k = u >> 4, nc = (u & 15) << 2;
        float4 v = *(const float4*)(xb + (size_t)k * NSP + nc);
        *(float4*)(stage + k * 68 + nc) = v;
    }
    __syncthreads();

    // phase 2: transpose-convert to bf16 hi/lo [n][k] layout
#pragma unroll
    for (int it = 0; it < 4; it++) {
        int v = tid + it * 256;
        int n = v & 63, k8 = v >> 6;
        float f[8];
#pragma unroll
        for (int j = 0; j < 8; j++) f[j] = stage[(k8 * 8 + j) * 68 + n];
        u32 hw[4], lw[4];
#pragma unroll
        for (int jj = 0; jj < 2; jj++) {
            float4 q4 = make_float4(f[4 * jj], f[4 * jj + 1], f[4 * jj + 2], f[4 * jj + 3]);
            split4(q4, hw[2 * jj], hw[2 * jj + 1], lw[2 * jj], lw[2 * jj + 1]);
        }
        u32 off = n * 272 + k8 * 16;
        *(uint4*)(sm + oBh + off) = make_uint4(hw[0], hw[1], hw[2], hw[3]);
        *(uint4*)(sm + oBl + off) = make_uint4(lw[0], lw[1], lw[2], lw[3]);
    }
    __syncthreads();

    const int l = tid & 31, wid = tid >> 5;
    const int wm = (wid & 3) * 32;
    const int nh = (wid >> 2) * 32;
    const u32 aoff = (u32)((wm + (l & 15)) * 272 + (l >> 4) * 16);
    const u32 boff = (u32)((nh + (l & 7) + ((l >> 4) << 3)) * 272 + (((l >> 3) & 1) << 4));

    for (int rb = 0; rb < 3; rb++) {
        {
            const uint4* gh = (const uint4*)(g_Wh + (size_t)rb * 128 * 128);
            const uint4* gl = (const uint4*)(g_Wl + (size_t)rb * 128 * 128);
#pragma unroll
            for (int it = 0; it < 8; it++) {
                int u = tid + it * 256;
                int r = u >> 4, c = u & 15;
                u32 off = r * 272 + c * 16;
                *(uint4*)(sm + oAh + off) = gh[r * 16 + c];
                *(uint4*)(sm + oAl + off) = gl[r * 16 + c];
            }
        }
        __syncthreads();

        float acc[2][4][4];
#pragma unroll
        for (int mt = 0; mt < 2; mt++)
#pragma unroll
            for (int nt = 0; nt < 4; nt++)
#pragma unroll
                for (int q = 0; q < 4; q++) acc[mt][nt][q] = 0.f;

#pragma unroll
        for (int kc = 0; kc < 8; kc++) {
            u32 ah[2][4], al_[2][4], bhf[2][4], blf[2][4];
#pragma unroll
            for (int mt = 0; mt < 2; mt++) {
                u32 o = aoff + mt * (16 * 272) + kc * 32;
                ldm4(ah[mt],  sbase + oAh + o);
                ldm4(al_[mt], sbase + oAl + o);
            }
#pragma unroll
            for (int p = 0; p < 2; p++) {
                u32 o = boff + p * (16 * 272) + kc * 32;
                ldm4(bhf[p], sbase + oBh + o);
                ldm4(blf[p], sbase + oBl + o);
            }
#pragma unroll
            for (int mt = 0; mt < 2; mt++)
#pragma unroll
                for (int nt = 0; nt < 4; nt++) {
                    int p = nt >> 1, q = (nt & 1) * 2;
                    mma16816(acc[mt][nt], ah[mt],  bhf[p][q], bhf[p][q + 1]);
                    mma16816(acc[mt][nt], al_[mt], bhf[p][q], bhf[p][q + 1]);
                    mma16816(acc[mt][nt], ah[mt],  blf[p][q], blf[p][q + 1]);
                }
        }

        float* outp = g_qkv + ((size_t)b * 384 + rb * 128) * NSP + t * 64;
#pragma unroll
        for (int mt = 0; mt < 2; mt++)
#pragma unroll
            for (int rh = 0; rh < 2; rh++) {
                int row = wm + mt * 16 + (l >> 2) + rh * 8;
#pragma unroll
                for (int nt = 0; nt < 4; nt++) {
                    int col = nh + nt * 8 + (l & 3) * 2;
                    float2 v2 = make_float2(acc[mt][nt][rh * 2], acc[mt][nt][rh * 2 + 1]);
                    *(float2*)(outp + (size_t)row * NSP + col) = v2;
                }
            }
        __syncthreads();
    }
}

// ---------------------------------------------------------------------------
// Kernel 2: Sp[d][e] = sum_n exp(k[d,n])*v[e,n] via split-bf16 mma; Z exact.
// grid = (4 heads, 4 slabs of 1024 n, 32 batches)
// ---------------------------------------------------------------------------
__global__ void __launch_bounds__(256) k_reduce_kv() {
    __shared__ __align__(16) char sm2[34816 + 4224];
    const u32 sbase = (u32)__cvta_generic_to_shared(sm2);
    const u32 oAh = 0, oAl = 8704, oBh = 17408, oBl = 26112;
    float* sbuf = (float*)(sm2 + 34816);
    const int h = blockIdx.x, p = blockIdx.y, b = blockIdx.z;
    const int tid = threadIdx.x;
    const int l = tid & 31, w = tid >> 5;
    const float* kb = g_qkv + ((size_t)b * 384 + 128 + h * DH) * NSP + p * 1024;
    const float* vb = g_qkv + ((size_t)b * 384 + 256 + h * DH) * NSP + p * 1024;

    const int mt = w & 1, np = (w >> 1) & 1, kh = w >> 2;
    const u32 aoff = (u32)((mt * 16 + (l & 15)) * 272 + (l >> 4) * 16);
    const u32 boff = (u32)((np * 16 + (l & 7) + ((l >> 4) << 3)) * 272 + (((l >> 3) & 1) << 4));

    float acc[2][4];
#pragma unroll
    for (int g = 0; g < 2; g++)
#pragma unroll
        for (int q = 0; q < 4; q++) acc[g][q] = 0.f;
    float zreg[4] = {0.f, 0.f, 0.f, 0.f};

    for (int ch = 0; ch < 8; ch++) {
        __syncthreads();
#pragma unroll
        for (int i = 0; i < 4; i++) {
            int d = w + i * 8;
            float4 kv = *(const float4*)(kb + (size_t)d * NSP + ch * 128 + l * 4);
            float4 ev;
            if ((d & 15) < 12) {
                ev.x = exp_poly(kv.x); ev.y = exp_poly(kv.y);
                ev.z = exp_poly(kv.z); ev.w = exp_poly(kv.w);
            } else {
                ev.x = __expf(kv.x); ev.y = __expf(kv.y);
                ev.z = __expf(kv.z); ev.w = __expf(kv.w);
            }
            float s4 = ev.x + ev.y + ev.z + ev.w;
            s4 += __shfl_xor_sync(0xffffffffu, s4, 1);
            s4 += __shfl_xor_sync(0xffffffffu, s4, 2);
            s4 += __shfl_xor_sync(0xffffffffu, s4, 4);
            s4 += __shfl_xor_sync(0xffffffffu, s4, 8);
            s4 += __shfl_xor_sync(0xffffffffu, s4, 16);
            zreg[i] += s4;
            u32 h0, h1, l0, l1;
            split4(ev, h0, h1, l0, l1);
            *(uint2*)(sm2 + oAh + d * 272 + l * 8) = make_uint2(h0, h1);
            *(uint2*)(sm2 + oAl + d * 272 + l * 8) = make_uint2(l0, l1);
        }
#pragma unroll
        for (int i = 0; i < 4; i++) {
            int e = w + i * 8;
            float4 vv = *(const float4*)(vb + (size_t)e * NSP + ch * 128 + l * 4);
            u32 h0, h1, l0, l1;
            split4(vv, h0, h1, l0, l1);
            *(uint2*)(sm2 + oBh + e * 272 + l * 8) = make_uint2(h0, h1);
            *(uint2*)(sm2 + oBl + e * 272 + l * 8) = make_uint2(l0, l1);
        }
        __syncthreads();
#pragma unroll
        for (int kc2 = 0; kc2 < 4; kc2++) {
            int kc = kh * 4 + kc2;
            u32 ah[4], al_[4], bh_[4], bl_[4];
            ldm4(ah,  sbase + oAh + aoff + kc * 32);
            ldm4(al_, sbase + oAl + aoff + kc * 32);
            ldm4(bh_, sbase + oBh + boff + kc * 32);
            ldm4(bl_, sbase + oBl + boff + kc * 32);
#pragma unroll
            for (int g = 0; g < 2; g++) {
                mma16816(acc[g], ah,  bh_[g * 2], bh_[g * 2 + 1]);
                mma16816(acc[g], al_, bh_[g * 2], bh_[g * 2 + 1]);
                mma16816(acc[g], ah,  bl_[g * 2], bl_[g * 2 + 1]);
            }
        }
    }

    __syncthreads();
    if (kh == 0) {
#pragma unroll
        for (int g = 0; g < 2; g++)
#pragma unroll
            for (int rh = 0; rh < 2; rh++)
#pragma unroll
                for (int q = 0; q < 2; q++) {
                    int row = mt * 16 + (l >> 2) + rh * 8;
                    int col = np * 16 + g * 8 + (l & 3) * 2 + q;
                    sbuf[row * 33 + col] = acc[g][rh * 2 + q];
                }
    }
    __syncthreads();
    if (kh == 1) {
#pragma unroll
        for (int g = 0; g < 2; g++)
#pragma unroll
            for (int rh = 0; rh < 2; rh++)
#pragma unroll
                for (int q = 0; q < 2; q++) {
                    int row = mt * 16 + (l >> 2) + rh * 8;
                    int col = np * 16 + g * 8 + (l & 3) * 2 + q;
                    sbuf[row * 33 + col] += acc[g][rh * 2 + q];
                }
    }
    __syncthreads();
    float* Sp = g_Sp + (((size_t)(b * HEADS + h) * 4 + p) << 10);
#pragma unroll
    for (int i2 = 0; i2 < 4; i2++) {
        int idx = tid + i2 * 256;
        Sp[idx] = sbuf[(idx >> 5) * 33 + (idx & 31)];
    }
    if (l == 0) {
#pragma unroll
        for (int i = 0; i < 4; i++)
            g_Zp[((b * HEADS + h) * 4 + p) * 32 + w + i * 8] = zreg[i];
    }
}

// ---------------------------------------------------------------------------
// Kernel 3: ctx = (sum_p Sp)/Z; M_b = Wout∘ctx as bf16 hi/lo.
// grid = (32 batches, 8 o-slices); 4 partials.
// ---------------------------------------------------------------------------
__global__ void __launch_bounds__(256) k_ctx_M(const float* __restrict__ Wout) {
    __shared__ float ctxs[4 * 32 * 33];
    __shared__ float zs[128];
    const int b = blockIdx.x;
    const int og = blockIdx.y;
    const int tid = threadIdx.x;
    if (tid < 128) {
        float z = 0.f;
#pragma unroll
        for (int p = 0; p < 4; p++)
            z += g_Zp[((b * HEADS + (tid >> 5)) * 4 + p) * 32 + (tid & 31)];
        zs[tid] = z;
    }
    __syncthreads();
#pragma unroll
    for (int s2 = 0; s2 < 16; s2++) {
        int idx = tid + s2 * 256;
        int h = idx >> 10, d = (idx >> 5) & 31, e = idx & 31;
        float s = 0.f;
#pragma unroll
        for (int p = 0; p < 4; p++)
            s += g_Sp[(((size_t)(b * HEADS + h) * 4 + p) << 10) + (idx & 1023)];
        ctxs[h * 1056 + d * 33 + e] = s / zs[h * 32 + d];
    }
    __syncthreads();
    unsigned short* Mh = g_Mbh + (size_t)b * 16384;
    unsigned short* Ml = g_Mbl + (size_t)b * 16384;
#pragma unroll
    for (int s8 = 0; s8 < 8; s8++) {
        int pidx = og * 2048 + tid + s8 * 256;
        int o = pidx >> 7, hd = pidx & 127;
        int h = hd >> 5, dd = hd & 31;
        const float* wrow = Wout + o * 128 + h * 32;
        const float* crow = ctxs + h * 1056 + dd * 33;
        float s = 0.f;
#pragma unroll
        for (int e = 0; e < 32; e++) s += __ldg(wrow + e) * crow[e];
        __nv_bfloat16 hb = __float2bfloat16(s);
        float hf = __bfloat162float(hb);
        Mh[pidx] = __bfloat16_as_ushort(hb);
        Ml[pidx] = __bfloat16_as_ushort(__float2bfloat16(s - hf));
    }
}

// ---------------------------------------------------------------------------
// Kernel 4: out = LayerNorm( M_b @ softmax_d(q) + bout ), 64-wide tiles,
// 2 CTAs/SM, split-bf16 mma, exp hybrid p=12/16.
// smem: Bh[64][272], Bl; overlay { stage[128][68] } with Ah; Al; ln buffers.
// grid = (64 n-tiles, 32 batches)
// ---------------------------------------------------------------------------
#define SMEM_K4 107008
__global__ void __launch_bounds__(256) k_out(const float* __restrict__ bout,
                                             const float* __restrict__ lnw,
                                             const float* __restrict__ lnb,
                                             float* __restrict__ out) {
    extern __shared__ char sm[];
    const u32 sbase = (u32)__cvta_generic_to_shared(sm);
    const u32 oBh = 0, oBl = 17408, oAh = 34816, oAl = 69632;
    float* stage = (float*)(sm + oAh);
    float* ssum  = (float*)(sm + 104448);   // 4*64
    float* red   = (float*)(sm + 105472);   // 4*64
    float* meanv = (float*)(sm + 106496);   // 64
    float* rstd  = (float*)(sm + 106752);   // 64
    const int t = blockIdx.x, b = blockIdx.y;
    const int tid = threadIdx.x;
    const float* qb = g_qkv + (size_t)b * 384 * NSP + t * 64;

    // phase 1: exp(q) -> stage [128k][68]
#pragma unroll
    for (int it = 0; it < 8; it++) {
        int u = tid + it * 256;
        int k = u >> 4, nc = (u & 15) << 2;
        float4 v = *(const float4*)(qb + (size_t)k * NSP + nc);
        float4 ev;
        if ((k & 15) < 12) {
            ev.x = exp_poly(v.x); ev.y = exp_poly(v.y);
            ev.z = exp_poly(v.z); ev.w = exp_poly(v.w);
        } else {
            ev.x = __expf(v.x); ev.y = __expf(v.y);
            ev.z = __expf(v.z); ev.w = __expf(v.w);
        }
        *(float4*)(stage + k * 68 + nc) = ev;
    }
    __syncthreads();

    // phase 2: per (head, col) inverse sums (256 = 4 heads x 64 cols)
    {
        int n = tid & 63, hh = tid >> 6;
        float s = 0.f;
#pragma unroll
        for (int kk = 0; kk < 32; kk++) s += stage[(hh * 32 + kk) * 68 + n];
        ssum[hh * 64 + n] = 1.f / s;
    }
    __syncthreads();

    // phase 3: normalize + split to bf16 hi/lo [n][k]
#pragma unroll
    for (int it = 0; it < 4; it++) {
        int v = tid + it * 256;
        int n = v & 63, k8 = v >> 6;
        float rn_ = ssum[(k8 >> 2) * 64 + n];
        u32 hw[4], lw[4];
#pragma unroll
        for (int jj = 0; jj < 2; jj++) {
            float4 q4;
            q4.x = stage[(k8 * 8 + 4 * jj + 0) * 68 + n] * rn_;
            q4.y = stage[(k8 * 8 + 4 * jj + 1) * 68 + n] * rn_;
            q4.z = stage[(k8 * 8 + 4 * jj + 2) * 68 + n] * rn_;
            q4.w = stage[(k8 * 8 + 4 * jj + 3) * 68 + n] * rn_;
            split4(q4, hw[2 * jj], hw[2 * jj + 1], lw[2 * jj], lw[2 * jj + 1]);
        }
        u32 off = n * 272 + k8 * 16;
        *(uint4*)(sm + oBh + off) = make_uint4(hw[0], hw[1], hw[2], hw[3]);
        *(uint4*)(sm + oBl + off) = make_uint4(lw[0], lw[1], lw[2], lw[3]);
    }
    __syncthreads();

    // phase 4: A = pre-split M_b (overlays stage)
    {
        const uint4* gh = (const uint4*)(g_Mbh + (size_t)b * 16384);
        const uint4* gl = (const uint4*)(g_Mbl + (size_t)b * 16384);
#pragma unroll
        for (int it = 0; it < 8; it++) {
            int u = tid + it * 256;
            int r = u >> 4, c = u & 15;
            u32 off = r * 272 + c * 16;
            *(uint4*)(sm + oAh + off) = gh[r * 16 + c];
            *(uint4*)(sm + oAl + off) = gl[r * 16 + c];
        }
    }
    __syncthreads();

    const int l = tid & 31, wid = tid >> 5;
    const int wm = (wid & 3) * 32;
    const int nh = (wid >> 2) * 32;
    const u32 aoff = (u32)((wm + (l & 15)) * 272 + (l >> 4) * 16);
    const u32 boff = (u32)((nh + (l & 7) + ((l >> 4) << 3)) * 272 + (((l >> 3) & 1) << 4));

    float acc[2][4][4];
#pragma unroll
    for (int mt = 0; mt < 2; mt++)
#pragma unroll
        for (int nt = 0; nt < 4; nt++)
#pragma unroll
            for (int q = 0; q < 4; q++) acc[mt][nt][q] = 0.f;

#pragma unroll
    for (int kc = 0; kc < 8; kc++) {
        u32 ah[2][4], al_[2][4], bhf[2][4], blf[2][4];
#pragma unroll
        for (int mt = 0; mt < 2; mt++) {
            u32 o = aoff + mt * (16 * 272) + kc * 32;
            ldm4(ah[mt],  sbase + oAh + o);
            ldm4(al_[mt], sbase + oAl + o);
        }
#pragma unroll
        for (int p = 0; p < 2; p++) {
            u32 o = boff + p * (16 * 272) + kc * 32;
            ldm4(bhf[p], sbase + oBh + o);
            ldm4(blf[p], sbase + oBl + o);
        }
#pragma unroll
        for (int mt = 0; mt < 2; mt++)
#pragma unroll
            for (int nt = 0; nt < 4; nt++) {
                int p = nt >> 1, q = (nt & 1) * 2;
                mma16816(acc[mt][nt], ah[mt],  bhf[p][q], bhf[p][q + 1]);
                mma16816(acc[mt][nt], al_[mt], bhf[p][q], bhf[p][q + 1]);
                mma16816(acc[mt][nt], ah[mt],  blf[p][q], blf[p][q + 1]);
            }
    }

    // bias
#pragma unroll
    for (int mt = 0; mt < 2; mt++)
#pragma unroll
        for (int rh = 0; rh < 2; rh++) {
            float bo = __ldg(bout + wm + mt * 16 + (l >> 2) + rh * 8);
#pragma unroll
            for (int nt = 0; nt < 4; nt++) {
                acc[mt][nt][rh * 2 + 0] += bo;
                acc[mt][nt][rh * 2 + 1] += bo;
            }
        }

    // LN pass 1: means
#pragma unroll
    for (int q = 0; q < 2; q++) {
#pragma unroll
        for (int nt = 0; nt < 4; nt++) {
            float cs = acc[0][nt][q] + acc[0][nt][2 + q] + acc[1][nt][q] + acc[1][nt][2 + q];
            cs += __shfl_xor_sync(0xffffffffu, cs, 4);
            cs += __shfl_xor_sync(0xffffffffu, cs, 8);
            cs += __shfl_xor_sync(0xffffffffu, cs, 16);
            if (l < 4) red[(wid & 3) * 64 + nh + nt * 8 + l * 2 + q] = cs;
        }
    }
    __syncthreads();
    if (tid < 64) {
        float s = red[tid] + red[64 + tid] + red[128 + tid] + red[192 + tid];
        meanv[tid] = s * (1.f / 128.f);
    }
    __syncthreads();
    // LN pass 2: variances
#pragma unroll
    for (int q = 0; q < 2; q++) {
#pragma unroll
        for (int nt = 0; nt < 4; nt++) {
            float cm = meanv[nh + nt * 8 + (l & 3) * 2 + q];
            float d0 = acc[0][nt][q] - cm, d1 = acc[0][nt][2 + q] - cm;
            float d2 = acc[1][nt][q] - cm, d3 = acc[1][nt][2 + q] - cm;
            float cs = d0 * d0 + d1 * d1 + d2 * d2 + d3 * d3;
            cs += __shfl_xor_sync(0xffffffffu, cs, 4);
            cs += __shfl_xor_sync(0xffffffffu, cs, 8);
            cs += __shfl_xor_sync(0xffffffffu, cs, 16);
            if (l < 4) red[(wid & 3) * 64 + nh + nt * 8 + l * 2 + q] = cs;
        }
    }
    __syncthreads();
    if (tid < 64) {
        float s = red[tid] + red[64 + tid] + red[128 + tid] + red[192 + tid];
        rstd[tid] = rsqrtf(s * (1.f / 128.f) + EPS);
    }
    __syncthreads();

    // final store
#pragma unroll
    for (int mt = 0; mt < 2; mt++)
#pragma unroll
        for (int rh = 0; rh < 2; rh++) {
            int row = wm + mt * 16 + (l >> 2) + rh * 8;
            float lw = __ldg(lnw + row);
            float lb = __ldg(lnb + row);
#pragma unroll
            for (int nt = 0; nt < 4; nt++) {
                int col = nh + nt * 8 + (l & 3) * 2;
                float m0 = meanv[col], m1 = meanv[col + 1];
                float r0 = rstd[col], r1 = rstd[col + 1];
                float2 o2;
                o2.x = (acc[mt][nt][rh * 2 + 0] - m0) * r0 * lw + lb;
                o2.y = (acc[mt][nt][rh * 2 + 1] - m1) * r1 * lw + lb;
                *(float2*)(out + ((size_t)b * CDIM + row) * NSP + t * 64 + col) = o2;
            }
        }
}

// ---------------------------------------------------------------------------
extern "C" void kernel_launch(void* const* d_in, const int* in_sizes, int n_in,
                              void* d_out, int out_size) {
    const float* x    = (const float*)d_in[0];
    const float* Wqkv = (const float*)d_in[1];
    const float* Wout = (const float*)d_in[2];
    const float* bout = (const float*)d_in[3];
    const float* lnw  = (const float*)d_in[4];
    const float* lnb  = (const float*)d_in[5];
    float* out = (float*)d_out;

    cudaFuncSetAttribute(k_gemm_qkv, cudaFuncAttributeMaxDynamicSharedMemorySize, SMEM_K1);
    cudaFuncSetAttribute(k_out, cudaFuncAttributeMaxDynamicSharedMemorySize, SMEM_K4);

    k_splitW<<<48, 256>>>(Wqkv);
    k_gemm_qkv<<<dim3(64, B), 256, SMEM_K1>>>(x);
    k_reduce_kv<<<dim3(HEADS, 4, B), 256>>>();
    k_ctx_M<<<dim3(B, 8), 256>>>(Wout);
    k_out<<<dim3(64, B), 256, SMEM_K4>>>(bout, lnw, lnb, out);
}

// round 11
// speedup vs baseline: 2.3479x; 1.0603x over previous
#include <cuda_runtime.h>
#include <cuda_bf16.h>
#include <math.h>

#define B    32
#define CDIM 128
#define NSP  4096
#define HEADS 4
#define DH   32
#define EPS  1e-5f

typedef unsigned long long u64;
typedef unsigned int u32;

// ---------------- FFMA-only exp ----------------
__device__ __forceinline__ float exp_poly(float x) {
    float y = x * 1.4426950408889634f;
    float z = y + 12582912.0f;
    int   zb = __float_as_int(z);
    float n = z - 12582912.0f;
    float f = y - n;
    float p = 0.0096180f;
    p = fmaf(p, f, 0.0555041f);
    p = fmaf(p, f, 0.2402265f);
    p = fmaf(p, f, 0.6931472f);
    p = fmaf(p, f, 1.0f);
    return __int_as_float(__float_as_int(p) + (zb << 23));
}
__device__ __forceinline__ float exp_sel(float x, bool poly) {
    return poly ? exp_poly(x) : __expf(x);
}

// ---------------- mma.sync / ldmatrix wrappers ----------------
__device__ __forceinline__ void ldm4(u32* d, u32 addr) {
    asm volatile("ldmatrix.sync.aligned.m8n8.x4.shared.b16 {%0,%1,%2,%3},[%4];"
                 : "=r"(d[0]), "=r"(d[1]), "=r"(d[2]), "=r"(d[3]) : "r"(addr));
}
__device__ __forceinline__ void mma16816(float* c, const u32* a, u32 b0, u32 b1) {
    asm volatile("mma.sync.aligned.m16n8k16.row.col.f32.bf16.bf16.f32 "
                 "{%0,%1,%2,%3},{%4,%5,%6,%7},{%8,%9},{%0,%1,%2,%3};"
                 : "+f"(c[0]), "+f"(c[1]), "+f"(c[2]), "+f"(c[3])
                 : "r"(a[0]), "r"(a[1]), "r"(a[2]), "r"(a[3]), "r"(b0), "r"(b1));
}

// split a float4 into bf16x2 hi/lo packed words
__device__ __forceinline__ void split4(float4 v, u32& h0, u32& h1, u32& l0, u32& l1) {
    asm("cvt.rn.bf16x2.f32 %0,%1,%2;" : "=r"(h0) : "f"(v.y), "f"(v.x));
    asm("cvt.rn.bf16x2.f32 %0,%1,%2;" : "=r"(h1) : "f"(v.w), "f"(v.z));
    float r0 = v.x - __int_as_float((int)(h0 << 16));
    float r1 = v.y - __int_as_float((int)(h0 & 0xFFFF0000u));
    float r2 = v.z - __int_as_float((int)(h1 << 16));
    float r3 = v.w - __int_as_float((int)(h1 & 0xFFFF0000u));
    asm("cvt.rn.bf16x2.f32 %0,%1,%2;" : "=r"(l0) : "f"(r1), "f"(r0));
    asm("cvt.rn.bf16x2.f32 %0,%1,%2;" : "=r"(l1) : "f"(r3), "f"(r2));
}
// pack 2 consecutive elems -> (hi bf16x2, lo bf16x2)
__device__ __forceinline__ uint2 pack2(float x, float y) {
    u32 h, lo;
    asm("cvt.rn.bf16x2.f32 %0,%1,%2;" : "=r"(h) : "f"(y), "f"(x));
    float rx = x - __int_as_float((int)(h << 16));
    float ry = y - __int_as_float((int)(h & 0xFFFF0000u));
    asm("cvt.rn.bf16x2.f32 %0,%1,%2;" : "=r"(lo) : "f"(ry), "f"(rx));
    return make_uint2(h, lo);
}

// ---------------- scratch ----------------
__device__ float g_q[(size_t)B * CDIM * NSP];                 // exp(q) fp32
__device__ __align__(16) uint2 g_kp[(size_t)B * CDIM * 2048]; // exp(k) (hi,lo) per 2 elems
__device__ __align__(16) uint2 g_vp[(size_t)B * CDIM * 2048]; // v (hi,lo) per 2 elems
__device__ float g_Sp[(size_t)B * HEADS * 4 * DH * DH];
__device__ float g_Zp64[(size_t)B * 64 * 2 * 128];            // [b][t][half][row]
__device__ __align__(16) unsigned short g_Wh[384 * 128];
__device__ __align__(16) unsigned short g_Wl[384 * 128];
__device__ __align__(16) unsigned short g_Mbh[(size_t)B * 16384];
__device__ __align__(16) unsigned short g_Mbl[(size_t)B * 16384];

// ---------------------------------------------------------------------------
// Kernel 0: split Wqkv into bf16 hi/lo
// ---------------------------------------------------------------------------
__global__ void k_splitW(const float* __restrict__ W) {
    for (int i = blockIdx.x * blockDim.x + threadIdx.x; i < 384 * 128;
         i += gridDim.x * blockDim.x) {
        float w = W[i];
        __nv_bfloat16 hb = __float2bfloat16(w);
        float hf = __bfloat162float(hb);
        __nv_bfloat16 lb = __float2bfloat16(w - hf);
        g_Wh[i] = __bfloat16_as_ushort(hb);
        g_Wl[i] = __bfloat16_as_ushort(lb);
    }
}

// ---------------------------------------------------------------------------
// Kernel 1: qkv = Wqkv @ x (split-bf16 mma.sync, 64-wide n tiles, 2 CTA/SM)
// FUSED epilogue: rb=0 -> exp(q) fp32; rb=1 -> exp(k) + Z partials + bf16
// pair-pack; rb=2 -> v bf16 pair-pack.
// grid = (64 n-tiles, 32 batches), 256 threads (8 warps: 4 m x 2 n).
// ---------------------------------------------------------------------------
#define SMEM_K1 104448
__global__ void __launch_bounds__(256) k_gemm_qkv(const float* __restrict__ x) {
    extern __shared__ char sm[];
    const u32 sbase = (u32)__cvta_generic_to_shared(sm);
    const u32 oBh = 0, oBl = 17408, oAh = 34816, oAl = 69632;
    float* stage = (float*)(sm + oAh);       // overlays Ah region
    const int t = blockIdx.x, b = blockIdx.y;
    const int tid = threadIdx.x;
    const float* xb = x + (size_t)b * CDIM * NSP + t * 64;

    // phase 1: x tile [128k][64n] -> fp32 stage stride 68
#pragma unroll
    for (int it = 0; it < 8; it++) {
        int u = tid + it * 256;
        int k = u >> 4, nc = (u & 15) << 2;
        float4 v = *(const float4*)(xb + (size_t)k * NSP + nc);
        *(float4*)(stage + k * 68 + nc) = v;
    }
    __syncthreads();

    // phase 2: transpose-convert to bf16 hi/lo [n][k] layout
#pragma unroll
    for (int it = 0; it < 4; it++) {
        int v = tid + it * 256;
        int n = v & 63, k8 = v >> 6;
        float f[8];
#pragma unroll
        for (int j = 0; j < 8; j++) f[j] = stage[(k8 * 8 + j) * 68 + n];
        u32 hw[4], lw[4];
#pragma unroll
        for (int jj = 0; jj < 2; jj++) {
            float4 q4 = make_float4(f[4 * jj], f[4 * jj + 1], f[4 * jj + 2], f[4 * jj + 3]);
            split4(q4, hw[2 * jj], hw[2 * jj + 1], lw[2 * jj], lw[2 * jj + 1]);
        }
        u32 off = n * 272 + k8 * 16;
        *(uint4*)(sm + oBh + off) = make_uint4(hw[0], hw[1], hw[2], hw[3]);
        *(uint4*)(sm + oBl + off) = make_uint4(lw[0], lw[1], lw[2], lw[3]);
    }
    __syncthreads();

    const int l = tid & 31, wid = tid >> 5;
    const int wm = (wid & 3) * 32;
    const int nh = (wid >> 2) * 32;
    const u32 aoff = (u32)((wm + (l & 15)) * 272 + (l >> 4) * 16);
    const u32 boff = (u32)((nh + (l & 7) + ((l >> 4) << 3)) * 272 + (((l >> 3) & 1) << 4));

    for (int rb = 0; rb < 3; rb++) {
        {
            const uint4* gh = (const uint4*)(g_Wh + (size_t)rb * 128 * 128);
            const uint4* gl = (const uint4*)(g_Wl + (size_t)rb * 128 * 128);
#pragma unroll
            for (int it = 0; it < 8; it++) {
                int u = tid + it * 256;
                int r = u >> 4, c = u & 15;
                u32 off = r * 272 + c * 16;
                *(uint4*)(sm + oAh + off) = gh[r * 16 + c];
                *(uint4*)(sm + oAl + off) = gl[r * 16 + c];
            }
        }
        __syncthreads();

        float acc[2][4][4];
#pragma unroll
        for (int mt = 0; mt < 2; mt++)
#pragma unroll
            for (int nt = 0; nt < 4; nt++)
#pragma unroll
                for (int q = 0; q < 4; q++) acc[mt][nt][q] = 0.f;

#pragma unroll
        for (int kc = 0; kc < 8; kc++) {
            u32 ah[2][4], al_[2][4], bhf[2][4], blf[2][4];
#pragma unroll
            for (int mt = 0; mt < 2; mt++) {
                u32 o = aoff + mt * (16 * 272) + kc * 32;
                ldm4(ah[mt],  sbase + oAh + o);
                ldm4(al_[mt], sbase + oAl + o);
            }
#pragma unroll
            for (int p = 0; p < 2; p++) {
                u32 o = boff + p * (16 * 272) + kc * 32;
                ldm4(bhf[p], sbase + oBh + o);
                ldm4(blf[p], sbase + oBl + o);
            }
#pragma unroll
            for (int mt = 0; mt < 2; mt++)
#pragma unroll
                for (int nt = 0; nt < 4; nt++) {
                    int p = nt >> 1, q = (nt & 1) * 2;
                    mma16816(acc[mt][nt], ah[mt],  bhf[p][q], bhf[p][q + 1]);
                    mma16816(acc[mt][nt], al_[mt], bhf[p][q], bhf[p][q + 1]);
                    mma16816(acc[mt][nt], ah[mt],  blf[p][q], blf[p][q + 1]);
                }
        }

        if (rb == 0) {
            // q: exp (hybrid, compile-time pattern p=10/16), store fp32
#pragma unroll
            for (int mt = 0; mt < 2; mt++)
#pragma unroll
                for (int rh = 0; rh < 2; rh++) {
                    int row = wm + mt * 16 + (l >> 2) + rh * 8;
                    float* outp = g_q + ((size_t)b * CDIM + row) * NSP + t * 64;
#pragma unroll
                    for (int nt = 0; nt < 4; nt++) {
                        bool up = (mt == 0) || (rh == 0 && nt < 2);
                        float2 o2;
                        o2.x = exp_sel(acc[mt][nt][rh * 2 + 0], up);
                        o2.y = exp_sel(acc[mt][nt][rh * 2 + 1], up);
                        *(float2*)(outp + nh + nt * 8 + (l & 3) * 2) = o2;
                    }
                }
        } else if (rb == 1) {
            // k: exp in place
#pragma unroll
            for (int mt = 0; mt < 2; mt++)
#pragma unroll
                for (int rh = 0; rh < 2; rh++)
#pragma unroll
                    for (int nt = 0; nt < 4; nt++) {
                        bool up = (mt == 0) || (rh == 0 && nt < 2);
                        acc[mt][nt][rh * 2 + 0] = exp_sel(acc[mt][nt][rh * 2 + 0], up);
                        acc[mt][nt][rh * 2 + 1] = exp_sel(acc[mt][nt][rh * 2 + 1], up);
                    }
            // Z partials: per-row sum over this warp's 32 cols (2 shfls)
#pragma unroll
            for (int mt = 0; mt < 2; mt++)
#pragma unroll
                for (int rh = 0; rh < 2; rh++) {
                    int row = wm + mt * 16 + (l >> 2) + rh * 8;
                    float s = 0.f;
#pragma unroll
                    for (int nt = 0; nt < 4; nt++)
                        s += acc[mt][nt][rh * 2 + 0] + acc[mt][nt][rh * 2 + 1];
                    s += __shfl_xor_sync(0xffffffffu, s, 1);
                    s += __shfl_xor_sync(0xffffffffu, s, 2);
                    if ((l & 3) == 0)
                        g_Zp64[((size_t)b * 64 + t) * 256 + (wid >> 2) * 128 + row] = s;
                }
            // pair-pack store
#pragma unroll
            for (int mt = 0; mt < 2; mt++)
#pragma unroll
                for (int rh = 0; rh < 2; rh++) {
                    int row = wm + mt * 16 + (l >> 2) + rh * 8;
                    uint2* kr = g_kp + ((size_t)b * CDIM + row) * 2048 + t * 32 + (nh >> 1);
#pragma unroll
                    for (int nt = 0; nt < 4; nt++)
                        kr[nt * 4 + (l & 3)] =
                            pack2(acc[mt][nt][rh * 2 + 0], acc[mt][nt][rh * 2 + 1]);
                }
        } else {
            // v: pair-pack store only
#pragma unroll
            for (int mt = 0; mt < 2; mt++)
#pragma unroll
                for (int rh = 0; rh < 2; rh++) {
                    int row = wm + mt * 16 + (l >> 2) + rh * 8;
                    uint2* vr = g_vp + ((size_t)b * CDIM + row) * 2048 + t * 32 + (nh >> 1);
#pragma unroll
                    for (int nt = 0; nt < 4; nt++)
                        vr[nt * 4 + (l & 3)] =
                            pack2(acc[mt][nt][rh * 2 + 0], acc[mt][nt][rh * 2 + 1]);
                }
        }
        __syncthreads();
    }
}

// ---------------------------------------------------------------------------
// Kernel 2: Sp[d][e] = sum_n exp(k[d,n])*v[e,n] via split-bf16 mma.
// Pure load->STS->mma (exp/split/Z moved to k1).
// grid = (4 heads, 4 slabs of 1024 n, 32 batches)
// ---------------------------------------------------------------------------
__global__ void __launch_bounds__(256) k_reduce_kv() {
    __shared__ __align__(16) char sm2[34816 + 4224];
    const u32 sbase = (u32)__cvta_generic_to_shared(sm2);
    const u32 oAh = 0, oAl = 8704, oBh = 17408, oBl = 26112;
    float* sbuf = (float*)(sm2 + 34816);
    const int h = blockIdx.x, p = blockIdx.y, b = blockIdx.z;
    const int tid = threadIdx.x;
    const int l = tid & 31, w = tid >> 5;

    const int mt = w & 1, np = (w >> 1) & 1, kh = w >> 2;
    const u32 aoff = (u32)((mt * 16 + (l & 15)) * 272 + (l >> 4) * 16);
    const u32 boff = (u32)((np * 16 + (l & 7) + ((l >> 4) << 3)) * 272 + (((l >> 3) & 1) << 4));

    float acc[2][4];
#pragma unroll
    for (int g = 0; g < 2; g++)
#pragma unroll
        for (int q = 0; q < 4; q++) acc[g][q] = 0.f;

    for (int ch = 0; ch < 8; ch++) {
        __syncthreads();
#pragma unroll
        for (int i = 0; i < 4; i++) {
            int d = w + i * 8;
            const uint4* kr = (const uint4*)(g_kp + ((size_t)b * CDIM + h * 32 + d) * 2048);
            uint4 kk = kr[p * 256 + ch * 32 + l];
            *(uint2*)(sm2 + oAh + d * 272 + l * 8) = make_uint2(kk.x, kk.z);
            *(uint2*)(sm2 + oAl + d * 272 + l * 8) = make_uint2(kk.y, kk.w);
        }
#pragma unroll
        for (int i = 0; i < 4; i++) {
            int e = w + i * 8;
            const uint4* vr = (const uint4*)(g_vp + ((size_t)b * CDIM + h * 32 + e) * 2048);
            uint4 vv = vr[p * 256 + ch * 32 + l];
            *(uint2*)(sm2 + oBh + e * 272 + l * 8) = make_uint2(vv.x, vv.z);
            *(uint2*)(sm2 + oBl + e * 272 + l * 8) = make_uint2(vv.y, vv.w);
        }
        __syncthreads();
#pragma unroll
        for (int kc2 = 0; kc2 < 4; kc2++) {
            int kc = kh * 4 + kc2;
            u32 ah[4], al_[4], bh_[4], bl_[4];
            ldm4(ah,  sbase + oAh + aoff + kc * 32);
            ldm4(al_, sbase + oAl + aoff + kc * 32);
            ldm4(bh_, sbase + oBh + boff + kc * 32);
            ldm4(bl_, sbase + oBl + boff + kc * 32);
#pragma unroll
            for (int g = 0; g < 2; g++) {
                mma16816(acc[g], ah,  bh_[g * 2], bh_[g * 2 + 1]);
                mma16816(acc[g], al_, bh_[g * 2], bh_[g * 2 + 1]);
                mma16816(acc[g], ah,  bl_[g * 2], bl_[g * 2 + 1]);
            }
        }
    }

    __syncthreads();
    if (kh == 0) {
#pragma unroll
        for (int g = 0; g < 2; g++)
#pragma unroll
            for (int rh = 0; rh < 2; rh++)
#pragma unroll
                for (int q = 0; q < 2; q++) {
                    int row = mt * 16 + (l >> 2) + rh * 8;
                    int col = np * 16 + g * 8 + (l & 3) * 2 + q;
                    sbuf[row * 33 + col] = acc[g][rh * 2 + q];
                }
    }
    __syncthreads();
    if (kh == 1) {
#pragma unroll
        for (int g = 0; g < 2; g++)
#pragma unroll
            for (int rh = 0; rh < 2; rh++)
#pragma unroll
                for (int q = 0; q < 2; q++) {
                    int row = mt * 16 + (l >> 2) + rh * 8;
                    int col = np * 16 + g * 8 + (l & 3) * 2 + q;
                    sbuf[row * 33 + col] += acc[g][rh * 2 + q];
                }
    }
    __syncthreads();
    float* Sp = g_Sp + (((size_t)(b * HEADS + h) * 4 + p) << 10);
#pragma unroll
    for (int i2 = 0; i2 < 4; i2++) {
        int idx = tid + i2 * 256;
        Sp[idx] = sbuf[(idx >> 5) * 33 + (idx & 31)];
    }
}

// ---------------------------------------------------------------------------
// Kernel 3: ctx = (sum_p Sp)/Z (Z from 128-way k1 partials); M_b = Wout∘ctx
// as bf16 hi/lo.   grid = (32 batches, 8 o-slices)
// ---------------------------------------------------------------------------
__global__ void __launch_bounds__(256) k_ctx_M(const float* __restrict__ Wout) {
    __shared__ float ctxs[4 * 32 * 33];
    __shared__ float zs[128];
    const int b = blockIdx.x;
    const int og = blockIdx.y;
    const int tid = threadIdx.x;
    if (tid < 128) {
        const float* zp = g_Zp64 + (size_t)b * 16384 + tid;
        float z = 0.f;
#pragma unroll 8
        for (int s = 0; s < 128; s++) z += zp[(size_t)s * 128];
        zs[tid] = z;
    }
    __syncthreads();
#pragma unroll
    for (int s2 = 0; s2 < 16; s2++) {
        int idx = tid + s2 * 256;
        int h = idx >> 10, d = (idx >> 5) & 31, e = idx & 31;
        float s = 0.f;
#pragma unroll
        for (int p = 0; p < 4; p++)
            s += g_Sp[(((size_t)(b * HEADS + h) * 4 + p) << 10) + (idx & 1023)];
        ctxs[h * 1056 + d * 33 + e] = s / zs[h * 32 + d];
    }
    __syncthreads();
    unsigned short* Mh = g_Mbh + (size_t)b * 16384;
    unsigned short* Ml = g_Mbl + (size_t)b * 16384;
#pragma unroll
    for (int s8 = 0; s8 < 8; s8++) {
        int pidx = og * 2048 + tid + s8 * 256;
        int o = pidx >> 7, hd = pidx & 127;
        int h = hd >> 5, dd = hd & 31;
        const float* wrow = Wout + o * 128 + h * 32;
        const float* crow = ctxs + h * 1056 + dd * 33;
        float s = 0.f;
#pragma unroll
        for (int e = 0; e < 32; e++) s += __ldg(wrow + e) * crow[e];
        __nv_bfloat16 hb = __float2bfloat16(s);
        float hf = __bfloat162float(hb);
        Mh[pidx] = __bfloat16_as_ushort(hb);
        Ml[pidx] = __bfloat16_as_ushort(__float2bfloat16(s - hf));
    }
}

// ---------------------------------------------------------------------------
// Kernel 4: out = LayerNorm( M_b @ softmax_d(q) + bout ); q arrives pre-exp'd.
// grid = (64 n-tiles, 32 batches)
// ---------------------------------------------------------------------------
#define SMEM_K4 107008
__global__ void __launch_bounds__(256) k_out(const float* __restrict__ bout,
                                             const float* __restrict__ lnw,
                                             const float* __restrict__ lnb,
                                             float* __restrict__ out) {
    extern __shared__ char sm[];
    const u32 sbase = (u32)__cvta_generic_to_shared(sm);
    const u32 oBh = 0, oBl = 17408, oAh = 34816, oAl = 69632;
    float* stage = (float*)(sm + oAh);
    float* ssum  = (float*)(sm + 104448);
    float* red   = (float*)(sm + 105472);
    float* meanv = (float*)(sm + 106496);
    float* rstd  = (float*)(sm + 106752);
    const int t = blockIdx.x, b = blockIdx.y;
    const int tid = threadIdx.x;
    const float* qb = g_q + (size_t)b * CDIM * NSP + t * 64;

    // phase 1: copy exp(q) tile -> stage [128k][68]
#pragma unroll
    for (int it = 0; it < 8; it++) {
        int u = tid + it * 256;
        int k = u >> 4, nc = (u & 15) << 2;
        float4 v = *(const float4*)(qb + (size_t)k * NSP + nc);
        *(float4*)(stage + k * 68 + nc) = v;
    }
    __syncthreads();

    {
        int n = tid & 63, hh = tid >> 6;
        float s = 0.f;
#pragma unroll
        for (int kk = 0; kk < 32; kk++) s += stage[(hh * 32 + kk) * 68 + n];
        ssum[hh * 64 + n] = 1.f / s;
    }
    __syncthreads();

#pragma unroll
    for (int it = 0; it < 4; it++) {
        int v = tid + it * 256;
        int n = v & 63, k8 = v >> 6;
        float rn_ = ssum[(k8 >> 2) * 64 + n];
        u32 hw[4], lw[4];
#pragma unroll
        for (int jj = 0; jj < 2; jj++) {
            float4 q4;
            q4.x = stage[(k8 * 8 + 4 * jj + 0) * 68 + n] * rn_;
            q4.y = stage[(k8 * 8 + 4 * jj + 1) * 68 + n] * rn_;
            q4.z = stage[(k8 * 8 + 4 * jj + 2) * 68 + n] * rn_;
            q4.w = stage[(k8 * 8 + 4 * jj + 3) * 68 + n] * rn_;
            split4(q4, hw[2 * jj], hw[2 * jj + 1], lw[2 * jj], lw[2 * jj + 1]);
        }
        u32 off = n * 272 + k8 * 16;
        *(uint4*)(sm + oBh + off) = make_uint4(hw[0], hw[1], hw[2], hw[3]);
        *(uint4*)(sm + oBl + off) = make_uint4(lw[0], lw[1], lw[2], lw[3]);
    }
    __syncthreads();

    {
        const uint4* gh = (const uint4*)(g_Mbh + (size_t)b * 16384);
        const uint4* gl = (const uint4*)(g_Mbl + (size_t)b * 16384);
#pragma unroll
        for (int it = 0; it < 8; it++) {
            int u = tid + it * 256;
            int r = u >> 4, c = u & 15;
            u32 off = r * 272 + c * 16;
            *(uint4*)(sm + oAh + off) = gh[r * 16 + c];
            *(uint4*)(sm + oAl + off) = gl[r * 16 + c];
        }
    }
    __syncthreads();

    const int l = tid & 31, wid = tid >> 5;
    const int wm = (wid & 3) * 32;
    const int nh = (wid >> 2) * 32;
    const u32 aoff = (u32)((wm + (l & 15)) * 272 + (l >> 4) * 16);
    const u32 boff = (u32)((nh + (l & 7) + ((l >> 4) << 3)) * 272 + (((l >> 3) & 1) << 4));

    float acc[2][4][4];
#pragma unroll
    for (int mt = 0; mt < 2; mt++)
#pragma unroll
        for (int nt = 0; nt < 4; nt++)
#pragma unroll
            for (int q = 0; q < 4; q++) acc[mt][nt][q] = 0.f;

#pragma unroll
    for (int kc = 0; kc < 8; kc++) {
        u32 ah[2][4], al_[2][4], bhf[2][4], blf[2][4];
#pragma unroll
        for (int mt = 0; mt < 2; mt++) {
            u32 o = aoff + mt * (16 * 272) + kc * 32;
            ldm4(ah[mt],  sbase + oAh + o);
            ldm4(al_[mt], sbase + oAl + o);
        }
#pragma unroll
        for (int p = 0; p < 2; p++) {
            u32 o = boff + p * (16 * 272) + kc * 32;
            ldm4(bhf[p], sbase + oBh + o);
            ldm4(blf[p], sbase + oBl + o);
        }
#pragma unroll
        for (int mt = 0; mt < 2; mt++)
#pragma unroll
            for (int nt = 0; nt < 4; nt++) {
                int p = nt >> 1, q = (nt & 1) * 2;
                mma16816(acc[mt][nt], ah[mt],  bhf[p][q], bhf[p][q + 1]);
                mma16816(acc[mt][nt], al_[mt], bhf[p][q], bhf[p][q + 1]);
                mma16816(acc[mt][nt], ah[mt],  blf[p][q], blf[p][q + 1]);
            }
    }

#pragma unroll
    for (int mt = 0; mt < 2; mt++)
#pragma unroll
        for (int rh = 0; rh < 2; rh++) {
            float bo = __ldg(bout + wm + mt * 16 + (l >> 2) + rh * 8);
#pragma unroll
            for (int nt = 0; nt < 4; nt++) {
                acc[mt][nt][rh * 2 + 0] += bo;
                acc[mt][nt][rh * 2 + 1] += bo;
            }
        }

#pragma unroll
    for (int q = 0; q < 2; q++) {
#pragma unroll
        for (int nt = 0; nt < 4; nt++) {
            float cs = acc[0][nt][q] + acc[0][nt][2 + q] + acc[1][nt][q] + acc[1][nt][2 + q];
            cs += __shfl_xor_sync(0xffffffffu, cs, 4);
            cs += __shfl_xor_sync(0xffffffffu, cs, 8);
            cs += __shfl_xor_sync(0xffffffffu, cs, 16);
            if (l < 4) red[(wid & 3) * 64 + nh + nt * 8 + l * 2 + q] = cs;
        }
    }
    __syncthreads();
    if (tid < 64) {
        float s = red[tid] + red[64 + tid] + red[128 + tid] + red[192 + tid];
        meanv[tid] = s * (1.f / 128.f);
    }
    __syncthreads();
#pragma unroll
    for (int q = 0; q < 2; q++) {
#pragma unroll
        for (int nt = 0; nt < 4; nt++) {
            float cm = meanv[nh + nt * 8 + (l & 3) * 2 + q];
            float d0 = acc[0][nt][q] - cm, d1 = acc[0][nt][2 + q] - cm;
            float d2 = acc[1][nt][q] - cm, d3 = acc[1][nt][2 + q] - cm;
            float cs = d0 * d0 + d1 * d1 + d2 * d2 + d3 * d3;
            cs += __shfl_xor_sync(0xffffffffu, cs, 4);
            cs += __shfl_xor_sync(0xffffffffu, cs, 8);
            cs += __shfl_xor_sync(0xffffffffu, cs, 16);
            if (l < 4) red[(wid & 3) * 64 + nh + nt * 8 + l * 2 + q] = cs;
        }
    }
    __syncthreads();
    if (tid < 64) {
        float s = red[tid] + red[64 + tid] + red[128 + tid] + red[192 + tid];
        rstd[tid] = rsqrtf(s * (1.f / 128.f) + EPS);
    }
    __syncthreads();

#pragma unroll
    for (int mt = 0; mt < 2; mt++)
#pragma unroll
        for (int rh = 0; rh < 2; rh++) {
            int row = wm + mt * 16 + (l >> 2) + rh * 8;
            float lw = __ldg(lnw + row);
            float lb = __ldg(lnb + row);
#pragma unroll
            for (int nt = 0; nt < 4; nt++) {
                int col = nh + nt * 8 + (l & 3) * 2;
                float m0 = meanv[col], m1 = meanv[col + 1];
                float r0 = rstd[col], r1 = rstd[col + 1];
                float2 o2;
                o2.x = (acc[mt][nt][rh * 2 + 0] - m0) * r0 * lw + lb;
                o2.y = (acc[mt][nt][rh * 2 + 1] - m1) * r1 * lw + lb;
                *(float2*)(out + ((size_t)b * CDIM + row) * NSP + t * 64 + col) = o2;
            }
        }
}

// ---------------------------------------------------------------------------
extern "C" void kernel_launch(void* const* d_in, const int* in_sizes, int n_in,
                              void* d_out, int out_size) {
    const float* x    = (const float*)d_in[0];
    const float* Wqkv = (const float*)d_in[1];
    const float* Wout = (const float*)d_in[2];
    const float* bout = (const float*)d_in[3];
    const float* lnw  = (const float*)d_in[4];
    const float* lnb  = (const float*)d_in[5];
    float* out = (float*)d_out;

    cudaFuncSetAttribute(k_gemm_qkv, cudaFuncAttributeMaxDynamicSharedMemorySize, SMEM_K1);
    cudaFuncSetAttribute(k_out, cudaFuncAttributeMaxDynamicSharedMemorySize, SMEM_K4);

    k_splitW<<<48, 256>>>(Wqkv);
    k_gemm_qkv<<<dim3(64, B), 256, SMEM_K1>>>(x);
    k_reduce_kv<<<dim3(HEADS, 4, B), 256>>>();
    k_ctx_M<<<dim3(B, 8), 256>>>(Wout);
    k_out<<<dim3(64, B), 256, SMEM_K4>>>(bout, lnw, lnb, out);
}

// round 12
// speedup vs baseline: 2.4050x; 1.0243x over previous
#include <cuda_runtime.h>
#include <cuda_bf16.h>
#include <math.h>

#define B    32
#define CDIM 128
#define NSP  4096
#define HEADS 4
#define DH   32
#define EPS  1e-5f

typedef unsigned long long u64;
typedef unsigned int u32;

// ---------------- FFMA-only exp ----------------
__device__ __forceinline__ float exp_poly(float x) {
    float y = x * 1.4426950408889634f;
    float z = y + 12582912.0f;
    int   zb = __float_as_int(z);
    float n = z - 12582912.0f;
    float f = y - n;
    float p = 0.0096180f;
    p = fmaf(p, f, 0.0555041f);
    p = fmaf(p, f, 0.2402265f);
    p = fmaf(p, f, 0.6931472f);
    p = fmaf(p, f, 1.0f);
    return __int_as_float(__float_as_int(p) + (zb << 23));
}
__device__ __forceinline__ float exp_sel(float x, bool poly) {
    return poly ? exp_poly(x) : __expf(x);
}

// ---------------- mma.sync / ldmatrix wrappers ----------------
__device__ __forceinline__ void ldm4(u32* d, u32 addr) {
    asm volatile("ldmatrix.sync.aligned.m8n8.x4.shared.b16 {%0,%1,%2,%3},[%4];"
                 : "=r"(d[0]), "=r"(d[1]), "=r"(d[2]), "=r"(d[3]) : "r"(addr));
}
__device__ __forceinline__ void mma16816(float* c, const u32* a, u32 b0, u32 b1) {
    asm volatile("mma.sync.aligned.m16n8k16.row.col.f32.bf16.bf16.f32 "
                 "{%0,%1,%2,%3},{%4,%5,%6,%7},{%8,%9},{%0,%1,%2,%3};"
                 : "+f"(c[0]), "+f"(c[1]), "+f"(c[2]), "+f"(c[3])
                 : "r"(a[0]), "r"(a[1]), "r"(a[2]), "r"(a[3]), "r"(b0), "r"(b1));
}

// cp.async helpers
#define CPA16(saddr, gptr) \
    asm volatile("cp.async.cg.shared.global [%0],[%1],16;" :: "r"(saddr), "l"(gptr) : "memory")
#define CPA_COMMIT() asm volatile("cp.async.commit_group;" ::: "memory")
#define CPA_WAIT0()  asm volatile("cp.async.wait_group 0;" ::: "memory")

// split a float4 into bf16x2 hi/lo packed words
__device__ __forceinline__ void split4(float4 v, u32& h0, u32& h1, u32& l0, u32& l1) {
    asm("cvt.rn.bf16x2.f32 %0,%1,%2;" : "=r"(h0) : "f"(v.y), "f"(v.x));
    asm("cvt.rn.bf16x2.f32 %0,%1,%2;" : "=r"(h1) : "f"(v.w), "f"(v.z));
    float r0 = v.x - __int_as_float((int)(h0 << 16));
    float r1 = v.y - __int_as_float((int)(h0 & 0xFFFF0000u));
    float r2 = v.z - __int_as_float((int)(h1 << 16));
    float r3 = v.w - __int_as_float((int)(h1 & 0xFFFF0000u));
    asm("cvt.rn.bf16x2.f32 %0,%1,%2;" : "=r"(l0) : "f"(r1), "f"(r0));
    asm("cvt.rn.bf16x2.f32 %0,%1,%2;" : "=r"(l1) : "f"(r3), "f"(r2));
}
// pack 2 consecutive elems -> (hi bf16x2, lo bf16x2)
__device__ __forceinline__ uint2 pack2(float x, float y) {
    u32 h, lo;
    asm("cvt.rn.bf16x2.f32 %0,%1,%2;" : "=r"(h) : "f"(y), "f"(x));
    float rx = x - __int_as_float((int)(h << 16));
    float ry = y - __int_as_float((int)(h & 0xFFFF0000u));
    asm("cvt.rn.bf16x2.f32 %0,%1,%2;" : "=r"(lo) : "f"(ry), "f"(rx));
    return make_uint2(h, lo);
}

// ---------------- scratch ----------------
__device__ float g_q[(size_t)B * CDIM * NSP];                 // exp(q) fp32
__device__ __align__(16) uint2 g_kp[(size_t)B * CDIM * 2048]; // exp(k) (hi,lo) per 2 elems
__device__ __align__(16) uint2 g_vp[(size_t)B * CDIM * 2048]; // v (hi,lo) per 2 elems
__device__ float g_Sp[(size_t)B * HEADS * 4 * DH * DH];
__device__ float g_Zp64[(size_t)B * 64 * 2 * 128];            // [b][t][half][row]
__device__ __align__(16) unsigned short g_Wh[384 * 128];
__device__ __align__(16) unsigned short g_Wl[384 * 128];
__device__ __align__(16) unsigned short g_Mbh[(size_t)B * 16384];
__device__ __align__(16) unsigned short g_Mbl[(size_t)B * 16384];

// ---------------------------------------------------------------------------
// Kernel 0: split Wqkv into bf16 hi/lo
// ---------------------------------------------------------------------------
__global__ void k_splitW(const float* __restrict__ W) {
    for (int i = blockIdx.x * blockDim.x + threadIdx.x; i < 384 * 128;
         i += gridDim.x * blockDim.x) {
        float w = W[i];
        __nv_bfloat16 hb = __float2bfloat16(w);
        float hf = __bfloat162float(hb);
        __nv_bfloat16 lb = __float2bfloat16(w - hf);
        g_Wh[i] = __bfloat16_as_ushort(hb);
        g_Wl[i] = __bfloat16_as_ushort(lb);
    }
}

// ---------------------------------------------------------------------------
// Kernel 1: qkv = Wqkv @ x (split-bf16 mma.sync, 64-wide n tiles, 2 CTA/SM)
// FUSED epilogue: rb=0 -> exp(q) fp32; rb=1 -> exp(k) + Z partials + bf16
// pair-pack; rb=2 -> v bf16 pair-pack.   [unchanged from R11]
// ---------------------------------------------------------------------------
#define SMEM_K1 104448
__global__ void __launch_bounds__(256) k_gemm_qkv(const float* __restrict__ x) {
    extern __shared__ char sm[];
    const u32 sbase = (u32)__cvta_generic_to_shared(sm);
    const u32 oBh = 0, oBl = 17408, oAh = 34816, oAl = 69632;
    float* stage = (float*)(sm + oAh);
    const int t = blockIdx.x, b = blockIdx.y;
    const int tid = threadIdx.x;
    const float* xb = x + (size_t)b * CDIM * NSP + t * 64;

#pragma unroll
    for (int it = 0; it < 8; it++) {
        int u = tid + it * 256;
        int k = u >> 4, nc = (u & 15) << 2;
        float4 v = *(const float4*)(xb + (size_t)k * NSP + nc);
        *(float4*)(stage + k * 68 + nc) = v;
    }
    __syncthreads();

#pragma unroll
    for (int it = 0; it < 4; it++) {
        int v = tid + it * 256;
        int n = v & 63, k8 = v >> 6;
        float f[8];
#pragma unroll
        for (int j = 0; j < 8; j++) f[j] = stage[(k8 * 8 + j) * 68 + n];
        u32 hw[4], lw[4];
#pragma unroll
        for (int jj = 0; jj < 2; jj++) {
            float4 q4 = make_float4(f[4 * jj], f[4 * jj + 1], f[4 * jj + 2], f[4 * jj + 3]);
            split4(q4, hw[2 * jj], hw[2 * jj + 1], lw[2 * jj], lw[2 * jj + 1]);
        }
        u32 off = n * 272 + k8 * 16;
        *(uint4*)(sm + oBh + off) = make_uint4(hw[0], hw[1], hw[2], hw[3]);
        *(uint4*)(sm + oBl + off) = make_uint4(lw[0], lw[1], lw[2], lw[3]);
    }
    __syncthreads();

    const int l = tid & 31, wid = tid >> 5;
    const int wm = (wid & 3) * 32;
    const int nh = (wid >> 2) * 32;
    const u32 aoff = (u32)((wm + (l & 15)) * 272 + (l >> 4) * 16);
    const u32 boff = (u32)((nh + (l & 7) + ((l >> 4) << 3)) * 272 + (((l >> 3) & 1) << 4));

    for (int rb = 0; rb < 3; rb++) {
        {
            const uint4* gh = (const uint4*)(g_Wh + (size_t)rb * 128 * 128);
            const uint4* gl = (const uint4*)(g_Wl + (size_t)rb * 128 * 128);
#pragma unroll
            for (int it = 0; it < 8; it++) {
                int u = tid + it * 256;
                int r = u >> 4, c = u & 15;
                u32 off = r * 272 + c * 16;
                *(uint4*)(sm + oAh + off) = gh[r * 16 + c];
                *(uint4*)(sm + oAl + off) = gl[r * 16 + c];
            }
        }
        __syncthreads();

        float acc[2][4][4];
#pragma unroll
        for (int mt = 0; mt < 2; mt++)
#pragma unroll
            for (int nt = 0; nt < 4; nt++)
#pragma unroll
                for (int q = 0; q < 4; q++) acc[mt][nt][q] = 0.f;

#pragma unroll
        for (int kc = 0; kc < 8; kc++) {
            u32 ah[2][4], al_[2][4], bhf[2][4], blf[2][4];
#pragma unroll
            for (int mt = 0; mt < 2; mt++) {
                u32 o = aoff + mt * (16 * 272) + kc * 32;
                ldm4(ah[mt],  sbase + oAh + o);
                ldm4(al_[mt], sbase + oAl + o);
            }
#pragma unroll
            for (int p = 0; p < 2; p++) {
                u32 o = boff + p * (16 * 272) + kc * 32;
                ldm4(bhf[p], sbase + oBh + o);
                ldm4(blf[p], sbase + oBl + o);
            }
#pragma unroll
            for (int mt = 0; mt < 2; mt++)
#pragma unroll
                for (int nt = 0; nt < 4; nt++) {
                    int p = nt >> 1, q = (nt & 1) * 2;
                    mma16816(acc[mt][nt], ah[mt],  bhf[p][q], bhf[p][q + 1]);
                    mma16816(acc[mt][nt], al_[mt], bhf[p][q], bhf[p][q + 1]);
                    mma16816(acc[mt][nt], ah[mt],  blf[p][q], blf[p][q + 1]);
                }
        }

        if (rb == 0) {
#pragma unroll
            for (int mt = 0; mt < 2; mt++)
#pragma unroll
                for (int rh = 0; rh < 2; rh++) {
                    int row = wm + mt * 16 + (l >> 2) + rh * 8;
                    float* outp = g_q + ((size_t)b * CDIM + row) * NSP + t * 64;
#pragma unroll
                    for (int nt = 0; nt < 4; nt++) {
                        bool up = (mt == 0) || (rh == 0 && nt < 2);
                        float2 o2;
                        o2.x = exp_sel(acc[mt][nt][rh * 2 + 0], up);
                        o2.y = exp_sel(acc[mt][nt][rh * 2 + 1], up);
                        *(float2*)(outp + nh + nt * 8 + (l & 3) * 2) = o2;
                    }
                }
        } else if (rb == 1) {
#pragma unroll
            for (int mt = 0; mt < 2; mt++)
#pragma unroll
                for (int rh = 0; rh < 2; rh++)
#pragma unroll
                    for (int nt = 0; nt < 4; nt++) {
                        bool up = (mt == 0) || (rh == 0 && nt < 2);
                        acc[mt][nt][rh * 2 + 0] = exp_sel(acc[mt][nt][rh * 2 + 0], up);
                        acc[mt][nt][rh * 2 + 1] = exp_sel(acc[mt][nt][rh * 2 + 1], up);
                    }
#pragma unroll
            for (int mt = 0; mt < 2; mt++)
#pragma unroll
                for (int rh = 0; rh < 2; rh++) {
                    int row = wm + mt * 16 + (l >> 2) + rh * 8;
                    float s = 0.f;
#pragma unroll
                    for (int nt = 0; nt < 4; nt++)
                        s += acc[mt][nt][rh * 2 + 0] + acc[mt][nt][rh * 2 + 1];
                    s += __shfl_xor_sync(0xffffffffu, s, 1);
                    s += __shfl_xor_sync(0xffffffffu, s, 2);
                    if ((l & 3) == 0)
                        g_Zp64[((size_t)b * 64 + t) * 256 + (wid >> 2) * 128 + row] = s;
                }
#pragma unroll
            for (int mt = 0; mt < 2; mt++)
#pragma unroll
                for (int rh = 0; rh < 2; rh++) {
                    int row = wm + mt * 16 + (l >> 2) + rh * 8;
                    uint2* kr = g_kp + ((size_t)b * CDIM + row) * 2048 + t * 32 + (nh >> 1);
#pragma unroll
                    for (int nt = 0; nt < 4; nt++)
                        kr[nt * 4 + (l & 3)] =
                            pack2(acc[mt][nt][rh * 2 + 0], acc[mt][nt][rh * 2 + 1]);
                }
        } else {
#pragma unroll
            for (int mt = 0; mt < 2; mt++)
#pragma unroll
                for (int rh = 0; rh < 2; rh++) {
                    int row = wm + mt * 16 + (l >> 2) + rh * 8;
                    uint2* vr = g_vp + ((size_t)b * CDIM + row) * 2048 + t * 32 + (nh >> 1);
#pragma unroll
                    for (int nt = 0; nt < 4; nt++)
                        vr[nt * 4 + (l & 3)] =
                            pack2(acc[mt][nt][rh * 2 + 0], acc[mt][nt][rh * 2 + 1]);
                }
        }
        __syncthreads();
    }
}

// ---------------------------------------------------------------------------
// Kernel 2: Sp[d][e] = sum_n exp(k[d,n])*v[e,n] via split-bf16 mma.
// Register double-buffered: chunk ch+1 LDGs in flight during chunk ch mma.
// grid = (4 heads, 4 slabs of 1024 n, 32 batches)
// ---------------------------------------------------------------------------
__global__ void __launch_bounds__(256) k_reduce_kv() {
    __shared__ __align__(16) char sm2[34816 + 4224];
    const u32 sbase = (u32)__cvta_generic_to_shared(sm2);
    const u32 oAh = 0, oAl = 8704, oBh = 17408, oBl = 26112;
    float* sbuf = (float*)(sm2 + 34816);
    const int h = blockIdx.x, p = blockIdx.y, b = blockIdx.z;
    const int tid = threadIdx.x;
    const int l = tid & 31, w = tid >> 5;

    const int mt = w & 1, np = (w >> 1) & 1, kh = w >> 2;
    const u32 aoff = (u32)((mt * 16 + (l & 15)) * 272 + (l >> 4) * 16);
    const u32 boff = (u32)((np * 16 + (l & 7) + ((l >> 4) << 3)) * 272 + (((l >> 3) & 1) << 4));

    const uint4* kbase[4];
    const uint4* vbase[4];
#pragma unroll
    for (int i = 0; i < 4; i++) {
        kbase[i] = (const uint4*)(g_kp + ((size_t)b * CDIM + h * 32 + w + i * 8) * 2048)
                   + p * 256 + l;
        vbase[i] = (const uint4*)(g_vp + ((size_t)b * CDIM + h * 32 + w + i * 8) * 2048)
                   + p * 256 + l;
    }

    float acc[2][4];
#pragma unroll
    for (int g = 0; g < 2; g++)
#pragma unroll
        for (int q = 0; q < 4; q++) acc[g][q] = 0.f;

    uint4 kreg[4], vreg[4];
#pragma unroll
    for (int i = 0; i < 4; i++) { kreg[i] = kbase[i][0]; vreg[i] = vbase[i][0]; }

    for (int ch = 0; ch < 8; ch++) {
        __syncthreads();   // prev mma done reading smem
#pragma unroll
        for (int i = 0; i < 4; i++) {
            int d = w + i * 8;
            *(uint2*)(sm2 + oAh + d * 272 + l * 8) = make_uint2(kreg[i].x, kreg[i].z);
            *(uint2*)(sm2 + oAl + d * 272 + l * 8) = make_uint2(kreg[i].y, kreg[i].w);
            *(uint2*)(sm2 + oBh + d * 272 + l * 8) = make_uint2(vreg[i].x, vreg[i].z);
            *(uint2*)(sm2 + oBl + d * 272 + l * 8) = make_uint2(vreg[i].y, vreg[i].w);
        }
        __syncthreads();
        if (ch < 7) {
#pragma unroll
            for (int i = 0; i < 4; i++) {
                kreg[i] = kbase[i][(ch + 1) * 32];
                vreg[i] = vbase[i][(ch + 1) * 32];
            }
        }
#pragma unroll
        for (int kc2 = 0; kc2 < 4; kc2++) {
            int kc = kh * 4 + kc2;
            u32 ah[4], al_[4], bh_[4], bl_[4];
            ldm4(ah,  sbase + oAh + aoff + kc * 32);
            ldm4(al_, sbase + oAl + aoff + kc * 32);
            ldm4(bh_, sbase + oBh + boff + kc * 32);
            ldm4(bl_, sbase + oBl + boff + kc * 32);
#pragma unroll
            for (int g = 0; g < 2; g++) {
                mma16816(acc[g], ah,  bh_[g * 2], bh_[g * 2 + 1]);
                mma16816(acc[g], al_, bh_[g * 2], bh_[g * 2 + 1]);
                mma16816(acc[g], ah,  bl_[g * 2], bl_[g * 2 + 1]);
            }
        }
    }

    __syncthreads();
    if (kh == 0) {
#pragma unroll
        for (int g = 0; g < 2; g++)
#pragma unroll
            for (int rh = 0; rh < 2; rh++)
#pragma unroll
                for (int q = 0; q < 2; q++) {
                    int row = mt * 16 + (l >> 2) + rh * 8;
                    int col = np * 16 + g * 8 + (l & 3) * 2 + q;
                    sbuf[row * 33 + col] = acc[g][rh * 2 + q];
                }
    }
    __syncthreads();
    if (kh == 1) {
#pragma unroll
        for (int g = 0; g < 2; g++)
#pragma unroll
            for (int rh = 0; rh < 2; rh++)
#pragma unroll
                for (int q = 0; q < 2; q++) {
                    int row = mt * 16 + (l >> 2) + rh * 8;
                    int col = np * 16 + g * 8 + (l & 3) * 2 + q;
                    sbuf[row * 33 + col] += acc[g][rh * 2 + q];
                }
    }
    __syncthreads();
    float* Sp = g_Sp + (((size_t)(b * HEADS + h) * 4 + p) << 10);
#pragma unroll
    for (int i2 = 0; i2 < 4; i2++) {
        int idx = tid + i2 * 256;
        Sp[idx] = sbuf[(idx >> 5) * 33 + (idx & 31)];
    }
}

// ---------------------------------------------------------------------------
// Kernel 3: ctx = (sum_p Sp)/Z; M_b = Wout∘ctx as bf16 hi/lo.
// Z reduction parallelized across all 256 threads (64 loads each, L2-hot).
// grid = (32 batches, 8 o-slices)
// ---------------------------------------------------------------------------
__global__ void __launch_bounds__(256) k_ctx_M(const float* __restrict__ Wout) {
    __shared__ float ctxs[4 * 32 * 33];
    __shared__ float zpart[256];
    __shared__ float zs[128];
    const int b = blockIdx.x;
    const int og = blockIdx.y;
    const int tid = threadIdx.x;
    {
        // [b][t][half][row]: strides t:256, half:128, row:1
        const float* zp = g_Zp64 + (size_t)b * 16384 + (tid >> 7) * 128 + (tid & 127);
        float z = 0.f;
#pragma unroll 8
        for (int s = 0; s < 64; s++) z += zp[(size_t)s * 256];
        zpart[tid] = z;
    }
    __syncthreads();
    if (tid < 128) zs[tid] = zpart[tid] + zpart[tid + 128];
    __syncthreads();
#pragma unroll
    for (int s2 = 0; s2 < 16; s2++) {
        int idx = tid + s2 * 256;
        int h = idx >> 10, d = (idx >> 5) & 31, e = idx & 31;
        float s = 0.f;
#pragma unroll
        for (int p = 0; p < 4; p++)
            s += g_Sp[(((size_t)(b * HEADS + h) * 4 + p) << 10) + (idx & 1023)];
        ctxs[h * 1056 + d * 33 + e] = s / zs[h * 32 + d];
    }
    __syncthreads();
    unsigned short* Mh = g_Mbh + (size_t)b * 16384;
    unsigned short* Ml = g_Mbl + (size_t)b * 16384;
#pragma unroll
    for (int s8 = 0; s8 < 8; s8++) {
        int pidx = og * 2048 + tid + s8 * 256;
        int o = pidx >> 7, hd = pidx & 127;
        int h = hd >> 5, dd = hd & 31;
        const float* wrow = Wout + o * 128 + h * 32;
        const float* crow = ctxs + h * 1056 + dd * 33;
        float s = 0.f;
#pragma unroll
        for (int e = 0; e < 32; e++) s += __ldg(wrow + e) * crow[e];
        __nv_bfloat16 hb = __float2bfloat16(s);
        float hf = __bfloat162float(hb);
        Mh[pidx] = __bfloat16_as_ushort(hb);
        Ml[pidx] = __bfloat16_as_ushort(__float2bfloat16(s - hf));
    }
}

// ---------------------------------------------------------------------------
// Kernel 4: out = LayerNorm( M_b @ softmax_d(q) + bout ); q pre-exp'd.
// M_b tiles prefetched via cp.async (Al at start, Ah after stage frees).
// grid = (64 n-tiles, 32 batches)
// ---------------------------------------------------------------------------
#define SMEM_K4 107008
__global__ void __launch_bounds__(256) k_out(const float* __restrict__ bout,
                                             const float* __restrict__ lnw,
                                             const float* __restrict__ lnb,
                                             float* __restrict__ out) {
    extern __shared__ char sm[];
    const u32 sbase = (u32)__cvta_generic_to_shared(sm);
    const u32 oBh = 0, oBl = 17408, oAh = 34816, oAl = 69632;
    float* stage = (float*)(sm + oAh);
    float* ssum  = (float*)(sm + 104448);
    float* red   = (float*)(sm + 105472);
    float* meanv = (float*)(sm + 106496);
    float* rstd  = (float*)(sm + 106752);
    const int t = blockIdx.x, b = blockIdx.y;
    const int tid = threadIdx.x;
    const float* qb = g_q + (size_t)b * CDIM * NSP + t * 64;

    // prefetch Al (region free during phases 1-3)
    {
        const uint4* gl = (const uint4*)(g_Mbl + (size_t)b * 16384);
#pragma unroll
        for (int it = 0; it < 8; it++) {
            int u = tid + it * 256;
            int r = u >> 4, c = u & 15;
            CPA16(sbase + oAl + r * 272 + c * 16, gl + u);
        }
        CPA_COMMIT();
    }

    // phase 1: copy exp(q) tile -> stage [128k][68]
#pragma unroll
    for (int it = 0; it < 8; it++) {
        int u = tid + it * 256;
        int k = u >> 4, nc = (u & 15) << 2;
        float4 v = *(const float4*)(qb + (size_t)k * NSP + nc);
        *(float4*)(stage + k * 68 + nc) = v;
    }
    __syncthreads();

    {
        int n = tid & 63, hh = tid >> 6;
        float s = 0.f;
#pragma unroll
        for (int kk = 0; kk < 32; kk++) s += stage[(hh * 32 + kk) * 68 + n];
        ssum[hh * 64 + n] = 1.f / s;
    }
    __syncthreads();

#pragma unroll
    for (int it = 0; it < 4; it++) {
        int v = tid + it * 256;
        int n = v & 63, k8 = v >> 6;
        float rn_ = ssum[(k8 >> 2) * 64 + n];
        u32 hw[4], lw[4];
#pragma unroll
        for (int jj = 0; jj < 2; jj++) {
            float4 q4;
            q4.x = stage[(k8 * 8 + 4 * jj + 0) * 68 + n] * rn_;
            q4.y = stage[(k8 * 8 + 4 * jj + 1) * 68 + n] * rn_;
            q4.z = stage[(k8 * 8 + 4 * jj + 2) * 68 + n] * rn_;
            q4.w = stage[(k8 * 8 + 4 * jj + 3) * 68 + n] * rn_;
            split4(q4, hw[2 * jj], hw[2 * jj + 1], lw[2 * jj], lw[2 * jj + 1]);
        }
        u32 off = n * 272 + k8 * 16;
        *(uint4*)(sm + oBh + off) = make_uint4(hw[0], hw[1], hw[2], hw[3]);
        *(uint4*)(sm + oBl + off) = make_uint4(lw[0], lw[1], lw[2], lw[3]);
    }
    __syncthreads();   // stage fully consumed

    // phase 4: Ah via cp.async (overlays stage), wait both groups
    {
        const uint4* gh = (const uint4*)(g_Mbh + (size_t)b * 16384);
#pragma unroll
        for (int it = 0; it < 8; it++) {
            int u = tid + it * 256;
            int r = u >> 4, c = u & 15;
            CPA16(sbase + oAh + r * 272 + c * 16, gh + u);
        }
        CPA_COMMIT();
        CPA_WAIT0();
    }
    __syncthreads();

    const int l = tid & 31, wid = tid >> 5;
    const int wm = (wid & 3) * 32;
    const int nh = (wid >> 2) * 32;
    const u32 aoff = (u32)((wm + (l & 15)) * 272 + (l >> 4) * 16);
    const u32 boff = (u32)((nh + (l & 7) + ((l >> 4) << 3)) * 272 + (((l >> 3) & 1) << 4));

    float acc[2][4][4];
#pragma unroll
    for (int mt = 0; mt < 2; mt++)
#pragma unroll
        for (int nt = 0; nt < 4; nt++)
#pragma unroll
            for (int q = 0; q < 4; q++) acc[mt][nt][q] = 0.f;

#pragma unroll
    for (int kc = 0; kc < 8; kc++) {
        u32 ah[2][4], al_[2][4], bhf[2][4], blf[2][4];
#pragma unroll
        for (int mt = 0; mt < 2; mt++) {
            u32 o = aoff + mt * (16 * 272) + kc * 32;
            ldm4(ah[mt],  sbase + oAh + o);
            ldm4(al_[mt], sbase + oAl + o);
        }
#pragma unroll
        for (int p = 0; p < 2; p++) {
            u32 o = boff + p * (16 * 272) + kc * 32;
            ldm4(bhf[p], sbase + oBh + o);
            ldm4(blf[p], sbase + oBl + o);
        }
#pragma unroll
        for (int mt = 0; mt < 2; mt++)
#pragma unroll
            for (int nt = 0; nt < 4; nt++) {
                int p = nt >> 1, q = (nt & 1) * 2;
                mma16816(acc[mt][nt], ah[mt],  bhf[p][q], bhf[p][q + 1]);
                mma16816(acc[mt][nt], al_[mt], bhf[p][q], bhf[p][q + 1]);
                mma16816(acc[mt][nt], ah[mt],  blf[p][q], blf[p][q + 1]);
            }
    }

#pragma unroll
    for (int mt = 0; mt < 2; mt++)
#pragma unroll
        for (int rh = 0; rh < 2; rh++) {
            float bo = __ldg(bout + wm + mt * 16 + (l >> 2) + rh * 8);
#pragma unroll
            for (int nt = 0; nt < 4; nt++) {
                acc[mt][nt][rh * 2 + 0] += bo;
                acc[mt][nt][rh * 2 + 1] += bo;
            }
        }

#pragma unroll
    for (int q = 0; q < 2; q++) {
#pragma unroll
        for (int nt = 0; nt < 4; nt++) {
            float cs = acc[0][nt][q] + acc[0][nt][2 + q] + acc[1][nt][q] + acc[1][nt][2 + q];
            cs += __shfl_xor_sync(0xffffffffu, cs, 4);
            cs += __shfl_xor_sync(0xffffffffu, cs, 8);
            cs += __shfl_xor_sync(0xffffffffu, cs, 16);
            if (l < 4) red[(wid & 3) * 64 + nh + nt * 8 + l * 2 + q] = cs;
        }
    }
    __syncthreads();
    if (tid < 64) {
        float s = red[tid] + red[64 + tid] + red[128 + tid] + red[192 + tid];
        meanv[tid] = s * (1.f / 128.f);
    }
    __syncthreads();
#pragma unroll
    for (int q = 0; q < 2; q++) {
#pragma unroll
        for (int nt = 0; nt < 4; nt++) {
            float cm = meanv[nh + nt * 8 + (l & 3) * 2 + q];
            float d0 = acc[0][nt][q] - cm, d1 = acc[0][nt][2 + q] - cm;
            float d2 = acc[1][nt][q] - cm, d3 = acc[1][nt][2 + q] - cm;
            float cs = d0 * d0 + d1 * d1 + d2 * d2 + d3 * d3;
            cs += __shfl_xor_sync(0xffffffffu, cs, 4);
            cs += __shfl_xor_sync(0xffffffffu, cs, 8);
            cs += __shfl_xor_sync(0xffffffffu, cs, 16);
            if (l < 4) red[(wid & 3) * 64 + nh + nt * 8 + l * 2 + q] = cs;
        }
    }
    __syncthreads();
    if (tid < 64) {
        float s = red[tid] + red[64 + tid] + red[128 + tid] + red[192 + tid];
        rstd[tid] = rsqrtf(s * (1.f / 128.f) + EPS);
    }
    __syncthreads();

#pragma unroll
    for (int mt = 0; mt < 2; mt++)
#pragma unroll
        for (int rh = 0; rh < 2; rh++) {
            int row = wm + mt * 16 + (l >> 2) + rh * 8;
            float lw = __ldg(lnw + row);
            float lb = __ldg(lnb + row);
#pragma unroll
            for (int nt = 0; nt < 4; nt++) {
                int col = nh + nt * 8 + (l & 3) * 2;
                float m0 = meanv[col], m1 = meanv[col + 1];
                float r0 = rstd[col], r1 = rstd[col + 1];
                float2 o2;
                o2.x = (acc[mt][nt][rh * 2 + 0] - m0) * r0 * lw + lb;
                o2.y = (acc[mt][nt][rh * 2 + 1] - m1) * r1 * lw + lb;
                *(float2*)(out + ((size_t)b * CDIM + row) * NSP + t * 64 + col) = o2;
            }
        }
}

// ---------------------------------------------------------------------------
extern "C" void kernel_launch(void* const* d_in, const int* in_sizes, int n_in,
                              void* d_out, int out_size) {
    const float* x    = (const float*)d_in[0];
    const float* Wqkv = (const float*)d_in[1];
    const float* Wout = (const float*)d_in[2];
    const float* bout = (const float*)d_in[3];
    const float* lnw  = (const float*)d_in[4];
    const float* lnb  = (const float*)d_in[5];
    float* out = (float*)d_out;

    cudaFuncSetAttribute(k_gemm_qkv, cudaFuncAttributeMaxDynamicSharedMemorySize, SMEM_K1);
    cudaFuncSetAttribute(k_out, cudaFuncAttributeMaxDynamicSharedMemorySize, SMEM_K4);

    k_splitW<<<48, 256>>>(Wqkv);
    k_gemm_qkv<<<dim3(64, B), 256, SMEM_K1>>>(x);
    k_reduce_kv<<<dim3(HEADS, 4, B), 256>>>();
    k_ctx_M<<<dim3(B, 8), 256>>>(Wout);
    k_out<<<dim3(64, B), 256, SMEM_K4>>>(bout, lnw, lnb, out);
}